// round 14
// baseline (speedup 1.0000x reference)
#include <cuda_runtime.h>
#include <cuda_fp16.h>
#include <math.h>
#include <stdint.h>

#define Bsz 32
#define Ssz 512
#define Dsz 512
#define Hsz 8
#define Lsz 6
#define FFsz 2048
#define HDsz 64
#define Msz (Bsz*Ssz)          // 16384 rows

// ================= device scratch (no runtime allocation) =================
__device__ float g_X [Msz*Dsz];                 // residual stream fp32
__device__ __half g_Xh [Msz*Dsz];               // activations single fp16
__device__ __half g_QKVhi[Msz*3*Dsz];           // fused QKV out (fp16 hi)
__device__ __half g_QKVlo[Msz*3*Dsz];           // (lo used only for Q in attention)
__device__ __half g_Oh [Msz*Dsz];               // attention out fp16
__device__ float g_T  [Msz*Dsz];                // GEMM fp32 out (pre-LN)
__device__ __half g_Fh [Msz*FFsz];              // FF hidden fp16
// converted/transposed weights  [N,K] single fp16
__device__ __half g_Wqkv_h[Lsz*3*Dsz*Dsz];
__device__ __half g_Wot_h [Lsz*Dsz*Dsz];
__device__ __half g_W1t_h [Lsz*FFsz*Dsz];
__device__ __half g_W2t_h [Lsz*Dsz*FFsz];
__device__ float g_bqkv[Lsz*3*Dsz];
__device__ float g_C1[Bsz*(Dsz/2)];
__device__ float g_C2[Bsz*(Dsz/4)];

__device__ __forceinline__ float gelu_exact(float x) {
    return 0.5f * x * (1.0f + erff(x * 0.70710678118654752440f));
}
__device__ __forceinline__ void split_f16(float v, __half& h, __half& l) {
    h = __float2half_rn(v);
    l = __float2half_rn(v - __half2float(h));
}

// ================= PTX helpers (sm_80/90 baseline ISA only) =================
__device__ __forceinline__ uint32_t smem_u32(const void* p) {
    uint32_t a;
    asm("{ .reg .u64 t; cvta.to.shared.u64 t, %1; cvt.u32.u64 %0, t; }" : "=r"(a) : "l"(p));
    return a;
}
__device__ __forceinline__ void cp16(uint32_t saddr, const void* g) {
    asm volatile("cp.async.cg.shared.global [%0], [%1], 16;" :: "r"(saddr), "l"(g));
}
__device__ __forceinline__ void cp4(uint32_t saddr, const void* g) {
    asm volatile("cp.async.ca.shared.global [%0], [%1], 4;" :: "r"(saddr), "l"(g));
}
__device__ __forceinline__ void cp_commit() {
    asm volatile("cp.async.commit_group;" ::: "memory");
}
template<int N>
__device__ __forceinline__ void cp_wait() {
    asm volatile("cp.async.wait_group %0;" :: "n"(N) : "memory");
}
__device__ __forceinline__ void ldm_x4(uint32_t* r, uint32_t addr) {
    asm volatile("ldmatrix.sync.aligned.m8n8.x4.shared.b16 {%0,%1,%2,%3}, [%4];"
        : "=r"(r[0]), "=r"(r[1]), "=r"(r[2]), "=r"(r[3]) : "r"(addr));
}
__device__ __forceinline__ void ldm_x4_t(uint32_t* r, uint32_t addr) {
    asm volatile("ldmatrix.sync.aligned.m8n8.x4.trans.shared.b16 {%0,%1,%2,%3}, [%4];"
        : "=r"(r[0]), "=r"(r[1]), "=r"(r[2]), "=r"(r[3]) : "r"(addr));
}
__device__ __forceinline__ void mma_f16(float* d, const uint32_t* a, const uint32_t* b) {
    asm("mma.sync.aligned.m16n8k16.row.col.f32.f16.f16.f32 "
        "{%0,%1,%2,%3}, {%4,%5,%6,%7}, {%8,%9}, {%0,%1,%2,%3};"
        : "+f"(d[0]), "+f"(d[1]), "+f"(d[2]), "+f"(d[3])
        : "r"(a[0]), "r"(a[1]), "r"(a[2]), "r"(a[3]), "r"(b[0]), "r"(b[1]));
}

// ================= fp16 tensor-core GEMM (single-term, square tile) =================
// C[M,N] = A[M,K] x B[N,K]^T + bias, fp32 accum, single fp16 operands.
// CTA: 256 threads (8 warps, 4m x 2n), tile 128x128, warp tile 32x64,
// BK=32, 3-stage cp.async (2-chunk prefetch, issued after barrier -> race-free),
// single barrier per chunk. 2 CTAs/SM (16 warps/SM).
// EPI=0: fp32+bias. EPI=1: bias+GELU->fp16. EPI=2: bias->fp16 hi+lo.
#define GM_STRIDE 80                      // bytes per smem row (32 fp16 + 16B pad)
#define GM_TILE   (128*GM_STRIDE)        // 10240 bytes (A or B)
#define GM_STAGE  (2*GM_TILE)            // 20480 bytes
#define GM_SMEM   (3*GM_STAGE)           // 61440 bytes

template<int EPI>
__global__ __launch_bounds__(256, 2)
void mmagemm_kernel(const __half* __restrict__ A,
                    const __half* __restrict__ B,
                    const float* __restrict__ bias,
                    float* __restrict__ C,
                    __half* __restrict__ Chi,
                    __half* __restrict__ Clo,
                    int N, int K)
{
    extern __shared__ __align__(16) char smem[];
    const uint32_t sb = smem_u32(smem);

    const int tid  = threadIdx.x;
    const int lane = tid & 31;
    const int wid  = tid >> 5;
    const int wm   = wid >> 1;            // 0..3 (m offset wm*32)
    const int wn   = wid & 1;             // 0..1 (n offset wn*64)

    const int m0 = blockIdx.y * 128;
    const int n0 = blockIdx.x * 128;
    const int nk = K >> 5;                // K / 32 chunks (>= 16)

    // per stage: A 512 + B 512 = 1024 cp16; 4 per thread
    auto issue_stage = [&](int stage, int kc) {
        const uint32_t stb = sb + stage * GM_STAGE;
        const int kel = kc * 32;
        #pragma unroll
        for (int p = 0; p < 2; p++) {                 // A: 512 chunks
            const int c   = p * 256 + tid;
            const int row = c >> 2;
            const int j   = c & 3;
            cp16(stb + row * GM_STRIDE + j * 16,
                 A + (size_t)(m0 + row) * K + kel + j * 8);
        }
        #pragma unroll
        for (int p = 0; p < 2; p++) {                 // B: 512 chunks
            const int c   = p * 256 + tid;
            const int row = c >> 2;
            const int j   = c & 3;
            cp16(stb + GM_TILE + row * GM_STRIDE + j * 16,
                 B + (size_t)(n0 + row) * K + kel + j * 8);
        }
        cp_commit();
    };

    const int a_row  = (lane & 15);
    const int a_koff = (lane >> 4) * 16;
    const int bg     = lane >> 3;
    const int b_row  = (lane & 7) + ((bg >> 1) << 3);
    const int b_koff = (bg & 1) * 16;

    float acc[2][8][4];
    #pragma unroll
    for (int i = 0; i < 2; i++)
        #pragma unroll
        for (int j = 0; j < 8; j++)
            #pragma unroll
            for (int e = 0; e < 4; e++) acc[i][j][e] = 0.0f;

    issue_stage(0, 0);
    issue_stage(1, 1);

    for (int k = 0; k < nk; k++) {
        const int s = k % 3;
        if (k + 1 < nk) cp_wait<1>(); else cp_wait<0>();
        __syncthreads();
        if (k + 2 < nk) issue_stage((k + 2) % 3, k + 2);   // stage (k-1)%3, free after barrier

        const uint32_t stb = sb + s * GM_STAGE;
        const uint32_t sA = stb;
        const uint32_t sB = stb + GM_TILE;

        #pragma unroll
        for (int kk = 0; kk < 2; kk++) {
            const int kb = kk * 32;
            uint32_t ah[2][4];
            #pragma unroll
            for (int mt = 0; mt < 2; mt++) {
                const uint32_t off = (wm * 32 + mt * 16 + a_row) * GM_STRIDE + kb + a_koff;
                ldm_x4(ah[mt], sA + off);
            }
            #pragma unroll
            for (int np = 0; np < 4; np++) {
                uint32_t bh[4];
                const uint32_t off = (wn * 64 + np * 16 + b_row) * GM_STRIDE + kb + b_koff;
                ldm_x4(bh, sB + off);
                #pragma unroll
                for (int half = 0; half < 2; half++) {
                    const int nt = np * 2 + half, hf = half * 2;
                    uint32_t bf[2] = { bh[hf], bh[hf + 1] };
                    #pragma unroll
                    for (int mt = 0; mt < 2; mt++)
                        mma_f16(acc[mt][nt], ah[mt], bf);
                }
            }
        }
    }

    const int erow = lane >> 2;
    const int ecol = (lane & 3) * 2;
    #pragma unroll
    for (int mt = 0; mt < 2; mt++) {
        #pragma unroll
        for (int nt = 0; nt < 8; nt++) {
            const int col = n0 + wn * 64 + nt * 8 + ecol;
            const float bx = bias[col], by = bias[col + 1];
            #pragma unroll
            for (int half = 0; half < 2; half++) {
                const int row = m0 + wm * 32 + mt * 16 + erow + half * 8;
                float vx = acc[mt][nt][half * 2 + 0] + bx;
                float vy = acc[mt][nt][half * 2 + 1] + by;
                if (EPI == 0) {
                    float2 v = make_float2(vx, vy);
                    *reinterpret_cast<float2*>(C + (size_t)row * N + col) = v;
                } else if (EPI == 1) {
                    vx = gelu_exact(vx); vy = gelu_exact(vy);
                    __half2 hh; hh.x = __float2half_rn(vx); hh.y = __float2half_rn(vy);
                    *reinterpret_cast<__half2*>(Chi + (size_t)row * N + col) = hh;
                } else {
                    __half h0, l0, h1, l1;
                    split_f16(vx, h0, l0);
                    split_f16(vy, h1, l1);
                    __half2 hh; hh.x = h0; hh.y = h1;
                    __half2 ll; ll.x = l0; ll.y = l1;
                    *reinterpret_cast<__half2*>(Chi + (size_t)row * N + col) = hh;
                    *reinterpret_cast<__half2*>(Clo + (size_t)row * N + col) = ll;
                }
            }
        }
    }
}

// ================= fp16 tensor-core flash attention (2-term exact-Q) =================
#define AT_STRIDE 144                     // 64 fp16 = 128B + 16B pad
#define AT_TILE   (64*AT_STRIDE)          // 9216
#define AT_STAGE0 (2*AT_TILE)             // Q hi/lo
#define AT_STAGEB (2*AT_TILE)             // K, V (single each)
#define AT_MASK   (AT_STAGE0 + 2*AT_STAGEB)
#define AT_SMEM   (AT_MASK + 512)

__global__ __launch_bounds__(128)
void attn_mma_kernel(const __half* __restrict__ QKVhi,
                     const __half* __restrict__ QKVlo,
                     const int* __restrict__ mask,
                     const float* __restrict__ attn_bias_l,
                     __half* __restrict__ O)
{
    extern __shared__ __align__(16) char smem[];
    const uint32_t sb = smem_u32(smem);

    const int b  = blockIdx.z;
    const int h  = blockIdx.y;
    const int q0 = blockIdx.x * 64;
    const int tid  = threadIdx.x;
    const int lane = tid & 31;
    const int wq   = tid >> 5;
    const int RS   = 3 * Dsz;

    #pragma unroll
    for (int p = 0; p < 8; p++) {                   // Q hi/lo: 1024 chunks
        const int id  = p * 128 + tid;
        const int comp = id >> 9;
        const int cid  = id & 511;
        const int row  = cid >> 3;
        const int j    = cid & 7;
        const __half* src = (comp ? QKVlo : QKVhi)
            + (size_t)(b * Ssz + q0 + row) * RS + h * HDsz + j * 8;
        cp16(sb + comp * AT_TILE + row * AT_STRIDE + j * 16, src);
    }
    cp_commit();

    auto issue_kv = [&](int t) {
        const uint32_t stb = sb + AT_STAGE0 + (t & 1) * AT_STAGEB;
        #pragma unroll
        for (int p = 0; p < 8; p++) {               // K,V single: 1024 chunks
            const int id   = p * 128 + tid;
            const int comp = id >> 9;               // 0=K 1=V
            const int cid  = id & 511;
            const int row  = cid >> 3;
            const int j    = cid & 7;
            const int doff = comp ? 2 * Dsz : Dsz;
            const __half* src = QKVhi
                + (size_t)(b * Ssz + t * 64 + row) * RS + doff + h * HDsz + j * 8;
            cp16(stb + comp * AT_TILE + row * AT_STRIDE + j * 16, src);
        }
        if (tid < 64) cp4(sb + AT_MASK + (t & 1) * 256 + tid * 4, mask + b * Ssz + t * 64 + tid);
        cp_commit();
    };
    issue_kv(0);

    const int a_row  = (lane & 15);
    const int a_koff = (lane >> 4) * 16;
    const int bg     = lane >> 3;
    const int b_row  = (lane & 7) + ((bg >> 1) << 3);
    const int b_koff = (bg & 1) * 16;
    const int v_key  = ((lane >> 3) & 1) * 8 + (lane & 7);
    const int v_coff = (lane >> 4) * 16;

    const float scale = 0.125f;
    const float hbias = attn_bias_l[h];

    uint32_t qh[4][4], ql[4][4];
    float oacc[8][4];
    #pragma unroll
    for (int i = 0; i < 8; i++)
        #pragma unroll
        for (int e = 0; e < 4; e++) oacc[i][e] = 0.0f;
    float mr0 = -1e30f, mr1 = -1e30f, lr0 = 0.0f, lr1 = 0.0f;

    for (int t = 0; t < 8; t++) {
        cp_wait<0>();
        __syncthreads();
        if (t + 1 < 8) issue_kv(t + 1);

        if (t == 0) {
            #pragma unroll
            for (int kc = 0; kc < 4; kc++) {
                const uint32_t off = (wq * 16 + a_row) * AT_STRIDE + kc * 32 + a_koff;
                ldm_x4(qh[kc], sb + 0 * AT_TILE + off);
                ldm_x4(ql[kc], sb + 1 * AT_TILE + off);
            }
        }

        const uint32_t stb = sb + AT_STAGE0 + (t & 1) * AT_STAGEB;

        float sacc[8][4];
        #pragma unroll
        for (int i = 0; i < 8; i++)
            #pragma unroll
            for (int e = 0; e < 4; e++) sacc[i][e] = 0.0f;

        #pragma unroll
        for (int kc = 0; kc < 4; kc++) {
            #pragma unroll
            for (int np = 0; np < 4; np++) {
                uint32_t bh[4];
                const uint32_t off = (np * 16 + b_row) * AT_STRIDE + kc * 32 + b_koff;
                ldm_x4(bh, stb + 0 * AT_TILE + off);
                #pragma unroll
                for (int half = 0; half < 2; half++) {
                    const int nt = np * 2 + half, hf = half * 2;
                    uint32_t bf[2] = { bh[hf], bh[hf + 1] };
                    mma_f16(sacc[nt], qh[kc], bf);
                    mma_f16(sacc[nt], ql[kc], bf);
                }
            }
        }

        const int* msp = reinterpret_cast<const int*>(smem + AT_MASK + (t & 1) * 256);
        float vmax0 = -1e30f, vmax1 = -1e30f;
        #pragma unroll
        for (int nt = 0; nt < 8; nt++) {
            const int c0 = nt * 8 + (lane & 3) * 2;
            const int mk0 = msp[c0], mk1 = msp[c0 + 1];
            sacc[nt][0] = mk0 ? sacc[nt][0] * scale + hbias : -1e9f;
            sacc[nt][1] = mk1 ? sacc[nt][1] * scale + hbias : -1e9f;
            sacc[nt][2] = mk0 ? sacc[nt][2] * scale + hbias : -1e9f;
            sacc[nt][3] = mk1 ? sacc[nt][3] * scale + hbias : -1e9f;
            vmax0 = fmaxf(vmax0, fmaxf(sacc[nt][0], sacc[nt][1]));
            vmax1 = fmaxf(vmax1, fmaxf(sacc[nt][2], sacc[nt][3]));
        }
        vmax0 = fmaxf(vmax0, __shfl_xor_sync(0xffffffffu, vmax0, 1));
        vmax0 = fmaxf(vmax0, __shfl_xor_sync(0xffffffffu, vmax0, 2));
        vmax1 = fmaxf(vmax1, __shfl_xor_sync(0xffffffffu, vmax1, 1));
        vmax1 = fmaxf(vmax1, __shfl_xor_sync(0xffffffffu, vmax1, 2));
        const float mn0 = fmaxf(mr0, vmax0);
        const float mn1 = fmaxf(mr1, vmax1);
        const float al0 = __expf(mr0 - mn0);
        const float al1 = __expf(mr1 - mn1);

        uint32_t pah[4][4], pal[4][4];
        float rs0 = 0.0f, rs1 = 0.0f;
        #pragma unroll
        for (int nt = 0; nt < 8; nt++) {
            float p0 = __expf(sacc[nt][0] - mn0);
            float p1 = __expf(sacc[nt][1] - mn0);
            float p2 = __expf(sacc[nt][2] - mn1);
            float p3 = __expf(sacc[nt][3] - mn1);
            rs0 += p0 + p1; rs1 += p2 + p3;
            __half h0, l0, h1, l1, h2, l2, h3, l3;
            split_f16(p0, h0, l0); split_f16(p1, h1, l1);
            split_f16(p2, h2, l2); split_f16(p3, h3, l3);
            const int np = nt >> 1, pos = (nt & 1) * 2;
            __half2 t0; t0.x = h0; t0.y = h1;
            __half2 t1; t1.x = h2; t1.y = h3;
            __half2 t2; t2.x = l0; t2.y = l1;
            __half2 t3; t3.x = l2; t3.y = l3;
            pah[np][pos + 0] = *reinterpret_cast<uint32_t*>(&t0);
            pah[np][pos + 1] = *reinterpret_cast<uint32_t*>(&t1);
            pal[np][pos + 0] = *reinterpret_cast<uint32_t*>(&t2);
            pal[np][pos + 1] = *reinterpret_cast<uint32_t*>(&t3);
        }
        rs0 += __shfl_xor_sync(0xffffffffu, rs0, 1);
        rs0 += __shfl_xor_sync(0xffffffffu, rs0, 2);
        rs1 += __shfl_xor_sync(0xffffffffu, rs1, 1);
        rs1 += __shfl_xor_sync(0xffffffffu, rs1, 2);
        lr0 = lr0 * al0 + rs0;
        lr1 = lr1 * al1 + rs1;
        #pragma unroll
        for (int nt = 0; nt < 8; nt++) {
            oacc[nt][0] *= al0; oacc[nt][1] *= al0;
            oacc[nt][2] *= al1; oacc[nt][3] *= al1;
        }
        mr0 = mn0; mr1 = mn1;

        #pragma unroll
        for (int kc = 0; kc < 4; kc++) {
            #pragma unroll
            for (int np = 0; np < 4; np++) {
                uint32_t vh[4];
                const uint32_t voff = (kc * 16 + v_key) * AT_STRIDE + np * 32 + v_coff;
                ldm_x4_t(vh, stb + 1 * AT_TILE + voff);
                #pragma unroll
                for (int half = 0; half < 2; half++) {
                    const int nt = np * 2 + half, hf = half * 2;
                    uint32_t bf[2] = { vh[hf], vh[hf + 1] };
                    mma_f16(oacc[nt], pah[kc], bf);
                    mma_f16(oacc[nt], pal[kc], bf);
                }
            }
        }
    }

    const float inv0 = 1.0f / lr0;
    const float inv1 = 1.0f / lr1;
    const int row0 = b * Ssz + q0 + wq * 16 + (lane >> 2);
    const int row1 = row0 + 8;
    #pragma unroll
    for (int nt = 0; nt < 8; nt++) {
        const int col = h * HDsz + nt * 8 + (lane & 3) * 2;
        __half2 o0; o0.x = __float2half_rn(oacc[nt][0] * inv0);
        o0.y = __float2half_rn(oacc[nt][1] * inv0);
        __half2 o1; o1.x = __float2half_rn(oacc[nt][2] * inv1);
        o1.y = __float2half_rn(oacc[nt][3] * inv1);
        *reinterpret_cast<__half2*>(O + (size_t)row0 * Dsz + col) = o0;
        *reinterpret_cast<__half2*>(O + (size_t)row1 * Dsz + col) = o1;
    }
}

// ================= fused weight transpose + fp16 convert (single launch) =================
__global__ void wconv_all_kernel(const float* __restrict__ Wq, const float* __restrict__ Wk,
                                 const float* __restrict__ Wv, const float* __restrict__ Wo,
                                 const float* __restrict__ W1, const float* __restrict__ W2,
                                 __half* __restrict__ qkvh, __half* __restrict__ oth,
                                 __half* __restrict__ w1h,  __half* __restrict__ w2h)
{
    const int id = blockIdx.x;
    const int layer = id / 3072;
    const int r = id % 3072;
    const size_t DD = (size_t)Dsz * Dsz;
    const size_t DF = (size_t)Dsz * FFsz;

    const float* src;
    __half* dh;
    int K, N, bx, by;
    if (r < 1024) {
        const int which = r >> 8;
        const int t = r & 255;
        bx = t & 15; by = t >> 4; K = Dsz; N = Dsz;
        if (which == 0)      { src = Wq + layer * DD; dh = qkvh + layer * 3 * DD; }
        else if (which == 1) { src = Wk + layer * DD; dh = qkvh + layer * 3 * DD + DD; }
        else if (which == 2) { src = Wv + layer * DD; dh = qkvh + layer * 3 * DD + 2 * DD; }
        else                 { src = Wo + layer * DD; dh = oth + layer * DD; }
    } else if (r < 2048) {
        const int t = r - 1024;
        bx = t & 63; by = t >> 6; K = Dsz; N = FFsz;
        src = W1 + layer * DF; dh = w1h + layer * DF;
    } else {
        const int t = r - 2048;
        bx = t & 15; by = t >> 4; K = FFsz; N = Dsz;
        src = W2 + layer * DF; dh = w2h + layer * DF;
    }

    __shared__ float tbuf[32][33];
    const int k0 = by * 32, n0 = bx * 32;
    const int x = threadIdx.x, y = threadIdx.y;   // 32 x 8
    #pragma unroll
    for (int i = 0; i < 32; i += 8)
        tbuf[y + i][x] = src[(size_t)(k0 + y + i) * N + n0 + x];
    __syncthreads();
    #pragma unroll
    for (int i = 0; i < 32; i += 8) {
        float v = tbuf[x][y + i];
        dh[(size_t)(n0 + y + i) * K + k0 + x] = __float2half_rn(v);
    }
}

__global__ void bconcat_kernel(const float* __restrict__ bq, const float* __restrict__ bk,
                               const float* __restrict__ bv, float* __restrict__ out)
{
    int l = blockIdx.x, t = threadIdx.x;
    out[l*3*Dsz +          t] = bq[l*Dsz + t];
    out[l*3*Dsz +   Dsz +  t] = bk[l*Dsz + t];
    out[l*3*Dsz + 2*Dsz +  t] = bv[l*Dsz + t];
}

// ================= embedding =================
__global__ void embed_kernel(const int* __restrict__ ids,
                             const float* __restrict__ tok,
                             const float* __restrict__ pos,
                             const float* __restrict__ typ,
                             float* __restrict__ X,
                             __half* __restrict__ Xh)
{
    int row = blockIdx.x;
    int s   = row & (Ssz - 1);
    int c   = threadIdx.x * 4;
    int id  = ids[row];
    float4 t  = *reinterpret_cast<const float4*>(tok + (size_t)id * Dsz + c);
    float4 p  = *reinterpret_cast<const float4*>(pos + (size_t)s  * Dsz + c);
    float4 ty = *reinterpret_cast<const float4*>(typ + c);
    float v[4] = { t.x+p.x+ty.x, t.y+p.y+ty.y, t.z+p.z+ty.z, t.w+p.w+ty.w };
    *reinterpret_cast<float4*>(X + (size_t)row * Dsz + c) = make_float4(v[0],v[1],v[2],v[3]);
    #pragma unroll
    for (int j = 0; j < 4; j++)
        Xh[(size_t)row * Dsz + c + j] = __float2half_rn(v[j]);
}

// ================= add-residual + LayerNorm =================
__device__ __forceinline__ float warp_sum(float v) {
    #pragma unroll
    for (int o = 16; o; o >>= 1) v += __shfl_down_sync(0xffffffffu, v, o);
    return v;
}

__global__ __launch_bounds__(128)
void ln_kernel(const float* __restrict__ X, const float* __restrict__ Dlt,
               const float* __restrict__ gamma, const float* __restrict__ beta,
               float* __restrict__ Out, __half* __restrict__ Oh)
{
    int row = blockIdx.x;
    int tid = threadIdx.x;
    int c   = tid * 4;
    float4 v = *reinterpret_cast<const float4*>(X + (size_t)row * Dsz + c);
    if (Dlt) {
        float4 d = *reinterpret_cast<const float4*>(Dlt + (size_t)row * Dsz + c);
        v.x += d.x; v.y += d.y; v.z += d.z; v.w += d.w;
    }
    float sum = v.x + v.y + v.z + v.w;
    float sq  = v.x*v.x + v.y*v.y + v.z*v.z + v.w*v.w;

    __shared__ float s1[4], s2[4], smn, srd;
    int lane = tid & 31, w = tid >> 5;
    float ws = warp_sum(sum), wq = warp_sum(sq);
    if (lane == 0) { s1[w] = ws; s2[w] = wq; }
    __syncthreads();
    if (tid == 0) {
        float a = s1[0]+s1[1]+s1[2]+s1[3];
        float b = s2[0]+s2[1]+s2[2]+s2[3];
        float mean = a * (1.0f / Dsz);
        float var  = b * (1.0f / Dsz) - mean * mean;
        smn = mean; srd = rsqrtf(var + 1e-5f);
    }
    __syncthreads();
    float mean = smn, rstd = srd;
    float4 g  = *reinterpret_cast<const float4*>(gamma + c);
    float4 be = *reinterpret_cast<const float4*>(beta + c);
    float o[4];
    o[0] = (v.x - mean) * rstd * g.x + be.x;
    o[1] = (v.y - mean) * rstd * g.y + be.y;
    o[2] = (v.z - mean) * rstd * g.z + be.z;
    o[3] = (v.w - mean) * rstd * g.w + be.w;
    *reinterpret_cast<float4*>(Out + (size_t)row * Dsz + c) = make_float4(o[0],o[1],o[2],o[3]);
    if (Oh) {
        #pragma unroll
        for (int j = 0; j < 4; j++)
            Oh[(size_t)row * Dsz + c + j] = __float2half_rn(o[j]);
    }
}

// ================= classifier head =================
__global__ void cls1_kernel(const float* __restrict__ X, const float* __restrict__ W,
                            const float* __restrict__ b, float* __restrict__ out)
{
    int bi = blockIdx.x, j = threadIdx.x;
    const float* x = X + (size_t)(bi * Ssz) * Dsz;
    float s = 0.0f;
    for (int d = 0; d < Dsz; d++) s += x[d] * W[d * 256 + j];
    out[bi * 256 + j] = gelu_exact(s + b[j]);
}
__global__ void cls2_kernel(const float* __restrict__ Hh, const float* __restrict__ W,
                            const float* __restrict__ b, float* __restrict__ out)
{
    int bi = blockIdx.x, j = threadIdx.x;
    const float* x = Hh + bi * 256;
    float s = 0.0f;
    for (int d = 0; d < 256; d++) s += x[d] * W[d * 128 + j];
    out[bi * 128 + j] = gelu_exact(s + b[j]);
}
__global__ void cls3_kernel(const float* __restrict__ Hh, const float* __restrict__ W,
                            const float* __restrict__ b, float* __restrict__ out)
{
    int bi = threadIdx.x;
    const float* x = Hh + bi * 128;
    float s = 0.0f;
    for (int d = 0; d < 128; d++) s += x[d] * W[d];
    out[bi] = s + b[0];
}

// ================= host =================
extern "C" void kernel_launch(void* const* d_in, const int* in_sizes, int n_in,
                              void* d_out, int out_size)
{
    const int*   input_ids      = (const int*)d_in[0];
    const int*   attention_mask = (const int*)d_in[1];
    const float* tok_emb  = (const float*)d_in[2];
    const float* pos_emb  = (const float*)d_in[3];
    const float* type_emb = (const float*)d_in[4];
    const float* Wq  = (const float*)d_in[5];
    const float* bq  = (const float*)d_in[6];
    const float* Wk  = (const float*)d_in[7];
    const float* bk  = (const float*)d_in[8];
    const float* Wv  = (const float*)d_in[9];
    const float* bv  = (const float*)d_in[10];
    const float* Wo  = (const float*)d_in[11];
    const float* bo  = (const float*)d_in[12];
    const float* attn_bias = (const float*)d_in[13];
    const float* ln_a_s = (const float*)d_in[14];
    const float* ln_a_b = (const float*)d_in[15];
    const float* W1  = (const float*)d_in[16];
    const float* b1  = (const float*)d_in[17];
    const float* W2  = (const float*)d_in[18];
    const float* b2  = (const float*)d_in[19];
    const float* ln2_s = (const float*)d_in[20];
    const float* ln2_b = (const float*)d_in[21];
    const float* lnf_s = (const float*)d_in[22];
    const float* lnf_b = (const float*)d_in[23];
    const float* c1W = (const float*)d_in[24];
    const float* c1b = (const float*)d_in[25];
    const float* c2W = (const float*)d_in[26];
    const float* c2b = (const float*)d_in[27];
    const float* c3W = (const float*)d_in[28];
    const float* c3b = (const float*)d_in[29];

    float *pX, *pT, *pbqkv, *pC1, *pC2;
    __half *pXh, *pQKVhi, *pQKVlo, *pOh, *pFh;
    __half *pWqkvh, *pWoth, *pW1th, *pW2th;
    cudaGetSymbolAddress((void**)&pX,    g_X);
    cudaGetSymbolAddress((void**)&pXh,   g_Xh);
    cudaGetSymbolAddress((void**)&pQKVhi, g_QKVhi);
    cudaGetSymbolAddress((void**)&pQKVlo, g_QKVlo);
    cudaGetSymbolAddress((void**)&pOh,   g_Oh);
    cudaGetSymbolAddress((void**)&pT,    g_T);
    cudaGetSymbolAddress((void**)&pFh,   g_Fh);
    cudaGetSymbolAddress((void**)&pWqkvh, g_Wqkv_h);
    cudaGetSymbolAddress((void**)&pWoth, g_Wot_h);
    cudaGetSymbolAddress((void**)&pW1th, g_W1t_h);
    cudaGetSymbolAddress((void**)&pW2th, g_W2t_h);
    cudaGetSymbolAddress((void**)&pbqkv, g_bqkv);
    cudaGetSymbolAddress((void**)&pC1,   g_C1);
    cudaGetSymbolAddress((void**)&pC2,   g_C2);

    cudaFuncSetAttribute(mmagemm_kernel<0>, cudaFuncAttributeMaxDynamicSharedMemorySize, GM_SMEM);
    cudaFuncSetAttribute(mmagemm_kernel<1>, cudaFuncAttributeMaxDynamicSharedMemorySize, GM_SMEM);
    cudaFuncSetAttribute(mmagemm_kernel<2>, cudaFuncAttributeMaxDynamicSharedMemorySize, GM_SMEM);
    cudaFuncSetAttribute(attn_mma_kernel,   cudaFuncAttributeMaxDynamicSharedMemorySize, AT_SMEM);

    // launch #1: all weight conversions in one kernel
    wconv_all_kernel<<<Lsz*3072, dim3(32, 8)>>>(Wq, Wk, Wv, Wo, W1, W2,
        pWqkvh, pWoth, pW1th, pW2th);
    // launch #2
    bconcat_kernel<<<Lsz, Dsz>>>(bq, bk, bv, pbqkv);
    // launch #3
    embed_kernel<<<Msz, 128>>>(input_ids, tok_emb, pos_emb, type_emb, pX, pXh);

    for (int i = 0; i < Lsz; i++) {
        // QKV fused GEMM -> fp16 hi+lo       (launch #4 on first layer)
        mmagemm_kernel<2><<<dim3(3*Dsz/128, Msz/128), 256, GM_SMEM>>>(
            pXh, pWqkvh + (size_t)i*3*Dsz*Dsz,
            pbqkv + i*3*Dsz, nullptr, pQKVhi, pQKVlo, 3*Dsz, Dsz);

        // launch #5 on first layer
        attn_mma_kernel<<<dim3(Ssz/64, Hsz, Bsz), 128, AT_SMEM>>>(
            pQKVhi, pQKVlo, attention_mask, attn_bias + i*Hsz, pOh);

        // Wo GEMM                            (launch #6 on first layer -> ncu target)
        mmagemm_kernel<0><<<dim3(Dsz/128, Msz/128), 256, GM_SMEM>>>(
            pOh, pWoth + (size_t)i*Dsz*Dsz,
            bo + i*Dsz, pT, nullptr, nullptr, Dsz, Dsz);

        ln_kernel<<<Msz, 128>>>(pX, pT, ln_a_s + i*Dsz, ln_a_b + i*Dsz, pX, pXh);

        // FF1 (+GELU -> fp16)
        mmagemm_kernel<1><<<dim3(FFsz/128, Msz/128), 256, GM_SMEM>>>(
            pXh, pW1th + (size_t)i*FFsz*Dsz,
            b1 + i*FFsz, nullptr, pFh, nullptr, FFsz, Dsz);

        // FF2
        mmagemm_kernel<0><<<dim3(Dsz/128, Msz/128), 256, GM_SMEM>>>(
            pFh, pW2th + (size_t)i*Dsz*FFsz,
            b2 + i*Dsz, pT, nullptr, nullptr, Dsz, FFsz);

        ln_kernel<<<Msz, 128>>>(pX, pT, ln2_s + i*Dsz, ln2_b + i*Dsz, pX, pXh);
    }

    ln_kernel<<<Msz, 128>>>(pX, nullptr, lnf_s, lnf_b, pX, nullptr);

    cls1_kernel<<<Bsz, 256>>>(pX, c1W, c1b, pC1);
    cls2_kernel<<<Bsz, 128>>>(pC1, c2W, c2b, pC2);
    cls3_kernel<<<1, Bsz>>>(pC2, c3W, c3b, (float*)d_out);
}

// round 15
// speedup vs baseline: 1.1127x; 1.1127x over previous
#include <cuda_runtime.h>
#include <cuda_fp16.h>
#include <math.h>
#include <stdint.h>

#define Bsz 32
#define Ssz 512
#define Dsz 512
#define Hsz 8
#define Lsz 6
#define FFsz 2048
#define HDsz 64
#define Msz (Bsz*Ssz)          // 16384 rows

// ================= device scratch (no runtime allocation) =================
__device__ float g_X [Msz*Dsz];                 // residual stream fp32
__device__ __half g_Xh [Msz*Dsz];               // activations single fp16
__device__ __half g_QKVhi[Msz*3*Dsz];           // fused QKV out (fp16 hi)
__device__ __half g_QKVlo[Msz*3*Dsz];           // (lo used only for Q in attention)
__device__ __half g_Oh [Msz*Dsz];               // attention out fp16
__device__ float g_T  [Msz*Dsz];                // GEMM fp32 out (pre-LN)
__device__ __half g_Fh [Msz*FFsz];              // FF hidden fp16
// converted/transposed weights  [N,K] single fp16
__device__ __half g_Wqkv_h[Lsz*3*Dsz*Dsz];
__device__ __half g_Wot_h [Lsz*Dsz*Dsz];
__device__ __half g_W1t_h [Lsz*FFsz*Dsz];
__device__ __half g_W2t_h [Lsz*Dsz*FFsz];
__device__ float g_bqkv[Lsz*3*Dsz];
__device__ float g_C1[Bsz*(Dsz/2)];
__device__ float g_C2[Bsz*(Dsz/4)];

__device__ __forceinline__ float gelu_exact(float x) {
    return 0.5f * x * (1.0f + erff(x * 0.70710678118654752440f));
}
__device__ __forceinline__ void split_f16(float v, __half& h, __half& l) {
    h = __float2half_rn(v);
    l = __float2half_rn(v - __half2float(h));
}

// ================= PTX helpers (sm_80/90 baseline ISA only) =================
__device__ __forceinline__ uint32_t smem_u32(const void* p) {
    uint32_t a;
    asm("{ .reg .u64 t; cvta.to.shared.u64 t, %1; cvt.u32.u64 %0, t; }" : "=r"(a) : "l"(p));
    return a;
}
__device__ __forceinline__ void cp16(uint32_t saddr, const void* g) {
    asm volatile("cp.async.cg.shared.global [%0], [%1], 16;" :: "r"(saddr), "l"(g));
}
__device__ __forceinline__ void cp4(uint32_t saddr, const void* g) {
    asm volatile("cp.async.ca.shared.global [%0], [%1], 4;" :: "r"(saddr), "l"(g));
}
__device__ __forceinline__ void cp_commit() {
    asm volatile("cp.async.commit_group;" ::: "memory");
}
template<int N>
__device__ __forceinline__ void cp_wait() {
    asm volatile("cp.async.wait_group %0;" :: "n"(N) : "memory");
}
__device__ __forceinline__ void ldm_x4(uint32_t* r, uint32_t addr) {
    asm volatile("ldmatrix.sync.aligned.m8n8.x4.shared.b16 {%0,%1,%2,%3}, [%4];"
        : "=r"(r[0]), "=r"(r[1]), "=r"(r[2]), "=r"(r[3]) : "r"(addr));
}
__device__ __forceinline__ void ldm_x4_t(uint32_t* r, uint32_t addr) {
    asm volatile("ldmatrix.sync.aligned.m8n8.x4.trans.shared.b16 {%0,%1,%2,%3}, [%4];"
        : "=r"(r[0]), "=r"(r[1]), "=r"(r[2]), "=r"(r[3]) : "r"(addr));
}
__device__ __forceinline__ void mma_f16(float* d, const uint32_t* a, const uint32_t* b) {
    asm("mma.sync.aligned.m16n8k16.row.col.f32.f16.f16.f32 "
        "{%0,%1,%2,%3}, {%4,%5,%6,%7}, {%8,%9}, {%0,%1,%2,%3};"
        : "+f"(d[0]), "+f"(d[1]), "+f"(d[2]), "+f"(d[3])
        : "r"(a[0]), "r"(a[1]), "r"(a[2]), "r"(a[3]), "r"(b[0]), "r"(b[1]));
}

// ================= fp16 tensor-core GEMM (single-term, BK=64) =================
// C[M,N] = A[M,K] x B[N,K]^T + bias, fp32 accum, single fp16 operands.
// CTA: 128 threads (4 warps, 2m x 2n), tile 128x64, BK=64 (8 chunks for K=512:
// halves barrier/wait count vs BK=32), 2-stage cp.async, single barrier/chunk.
// 4 CTAs/SM (16 warps/SM), 216 KB smem/SM.
// EPI=0: fp32+bias. EPI=1: bias+GELU->fp16. EPI=2: bias->fp16 hi+lo.
#define GM_STRIDE 144                     // bytes per smem row (64 fp16 + 16B pad)
#define GM_TILEA  (128*GM_STRIDE)        // 18432 bytes
#define GM_TILEB  (64*GM_STRIDE)         // 9216 bytes
#define GM_STAGE  (GM_TILEA + GM_TILEB)  // 27648 bytes
#define GM_SMEM   (2*GM_STAGE)           // 55296 bytes

template<int EPI>
__global__ __launch_bounds__(128, 4)
void mmagemm_kernel(const __half* __restrict__ A,
                    const __half* __restrict__ B,
                    const float* __restrict__ bias,
                    float* __restrict__ C,
                    __half* __restrict__ Chi,
                    __half* __restrict__ Clo,
                    int N, int K)
{
    extern __shared__ __align__(16) char smem[];
    const uint32_t sb = smem_u32(smem);

    const int tid  = threadIdx.x;
    const int lane = tid & 31;
    const int wid  = tid >> 5;
    const int wm   = wid >> 1;            // 0..1 (m offset wm*64)
    const int wn   = wid & 1;             // 0..1 (n offset wn*32)

    const int m0 = blockIdx.y * 128;
    const int n0 = blockIdx.x * 64;
    const int nk = K >> 6;                // K / 64 chunks

    // per stage: A 1024 cp16 + B 512 cp16 = 1536; 12 per thread
    auto issue_stage = [&](int stage, int kc) {
        const uint32_t stb = sb + stage * GM_STAGE;
        const int kel = kc * 64;
        #pragma unroll
        for (int p = 0; p < 8; p++) {                 // A: 1024 chunks (128 rows x 8)
            const int c   = p * 128 + tid;
            const int row = c >> 3;
            const int j   = c & 7;
            cp16(stb + row * GM_STRIDE + j * 16,
                 A + (size_t)(m0 + row) * K + kel + j * 8);
        }
        #pragma unroll
        for (int p = 0; p < 4; p++) {                 // B: 512 chunks (64 rows x 8)
            const int c   = p * 128 + tid;
            const int row = c >> 3;
            const int j   = c & 7;
            cp16(stb + GM_TILEA + row * GM_STRIDE + j * 16,
                 B + (size_t)(n0 + row) * K + kel + j * 8);
        }
        cp_commit();
    };

    const int a_row  = (lane & 15);
    const int a_koff = (lane >> 4) * 16;
    const int bg     = lane >> 3;
    const int b_row  = (lane & 7) + ((bg >> 1) << 3);
    const int b_koff = (bg & 1) * 16;

    float acc[4][4][4];
    #pragma unroll
    for (int i = 0; i < 4; i++)
        #pragma unroll
        for (int j = 0; j < 4; j++)
            #pragma unroll
            for (int e = 0; e < 4; e++) acc[i][j][e] = 0.0f;

    issue_stage(0, 0);

    for (int k = 0; k < nk; k++) {
        const int s = k & 1;
        cp_wait<0>();
        __syncthreads();
        if (k + 1 < nk) issue_stage(s ^ 1, k + 1);

        const uint32_t stb = sb + s * GM_STAGE;
        const uint32_t sA = stb;
        const uint32_t sB = stb + GM_TILEA;

        #pragma unroll
        for (int kk = 0; kk < 4; kk++) {              // 4 x k16 within BK=64
            const int kb = kk * 32;                   // byte offset in row
            uint32_t ah[4][4];
            #pragma unroll
            for (int mt = 0; mt < 4; mt++) {
                const uint32_t off = (wm * 64 + mt * 16 + a_row) * GM_STRIDE + kb + a_koff;
                ldm_x4(ah[mt], sA + off);
            }
            uint32_t bh[2][4];
            #pragma unroll
            for (int np = 0; np < 2; np++) {
                const uint32_t off = (wn * 32 + np * 16 + b_row) * GM_STRIDE + kb + b_koff;
                ldm_x4(bh[np], sB + off);
            }
            #pragma unroll
            for (int mt = 0; mt < 4; mt++)
                #pragma unroll
                for (int nt = 0; nt < 4; nt++) {
                    const int np = nt >> 1, hf = (nt & 1) * 2;
                    uint32_t bf[2] = { bh[np][hf], bh[np][hf + 1] };
                    mma_f16(acc[mt][nt], ah[mt], bf);
                }
        }
    }

    const int erow = lane >> 2;
    const int ecol = (lane & 3) * 2;
    #pragma unroll
    for (int mt = 0; mt < 4; mt++) {
        #pragma unroll
        for (int nt = 0; nt < 4; nt++) {
            const int col = n0 + wn * 32 + nt * 8 + ecol;
            const float bx = bias[col], by = bias[col + 1];
            #pragma unroll
            for (int half = 0; half < 2; half++) {
                const int row = m0 + wm * 64 + mt * 16 + erow + half * 8;
                float vx = acc[mt][nt][half * 2 + 0] + bx;
                float vy = acc[mt][nt][half * 2 + 1] + by;
                if (EPI == 0) {
                    float2 v = make_float2(vx, vy);
                    *reinterpret_cast<float2*>(C + (size_t)row * N + col) = v;
                } else if (EPI == 1) {
                    vx = gelu_exact(vx); vy = gelu_exact(vy);
                    __half2 hh; hh.x = __float2half_rn(vx); hh.y = __float2half_rn(vy);
                    *reinterpret_cast<__half2*>(Chi + (size_t)row * N + col) = hh;
                } else {
                    __half h0, l0, h1, l1;
                    split_f16(vx, h0, l0);
                    split_f16(vy, h1, l1);
                    __half2 hh; hh.x = h0; hh.y = h1;
                    __half2 ll; ll.x = l0; ll.y = l1;
                    *reinterpret_cast<__half2*>(Chi + (size_t)row * N + col) = hh;
                    *reinterpret_cast<__half2*>(Clo + (size_t)row * N + col) = ll;
                }
            }
        }
    }
}

// ================= fp16 tensor-core flash attention (2-term exact-Q) =================
#define AT_STRIDE 144                     // 64 fp16 = 128B + 16B pad
#define AT_TILE   (64*AT_STRIDE)          // 9216
#define AT_STAGE0 (2*AT_TILE)             // Q hi/lo
#define AT_STAGEB (2*AT_TILE)             // K, V (single each)
#define AT_MASK   (AT_STAGE0 + 2*AT_STAGEB)
#define AT_SMEM   (AT_MASK + 512)

__global__ __launch_bounds__(128)
void attn_mma_kernel(const __half* __restrict__ QKVhi,
                     const __half* __restrict__ QKVlo,
                     const int* __restrict__ mask,
                     const float* __restrict__ attn_bias_l,
                     __half* __restrict__ O)
{
    extern __shared__ __align__(16) char smem[];
    const uint32_t sb = smem_u32(smem);

    const int b  = blockIdx.z;
    const int h  = blockIdx.y;
    const int q0 = blockIdx.x * 64;
    const int tid  = threadIdx.x;
    const int lane = tid & 31;
    const int wq   = tid >> 5;
    const int RS   = 3 * Dsz;

    #pragma unroll
    for (int p = 0; p < 8; p++) {                   // Q hi/lo: 1024 chunks
        const int id  = p * 128 + tid;
        const int comp = id >> 9;
        const int cid  = id & 511;
        const int row  = cid >> 3;
        const int j    = cid & 7;
        const __half* src = (comp ? QKVlo : QKVhi)
            + (size_t)(b * Ssz + q0 + row) * RS + h * HDsz + j * 8;
        cp16(sb + comp * AT_TILE + row * AT_STRIDE + j * 16, src);
    }
    cp_commit();

    auto issue_kv = [&](int t) {
        const uint32_t stb = sb + AT_STAGE0 + (t & 1) * AT_STAGEB;
        #pragma unroll
        for (int p = 0; p < 8; p++) {               // K,V single: 1024 chunks
            const int id   = p * 128 + tid;
            const int comp = id >> 9;               // 0=K 1=V
            const int cid  = id & 511;
            const int row  = cid >> 3;
            const int j    = cid & 7;
            const int doff = comp ? 2 * Dsz : Dsz;
            const __half* src = QKVhi
                + (size_t)(b * Ssz + t * 64 + row) * RS + doff + h * HDsz + j * 8;
            cp16(stb + comp * AT_TILE + row * AT_STRIDE + j * 16, src);
        }
        if (tid < 64) cp4(sb + AT_MASK + (t & 1) * 256 + tid * 4, mask + b * Ssz + t * 64 + tid);
        cp_commit();
    };
    issue_kv(0);

    const int a_row  = (lane & 15);
    const int a_koff = (lane >> 4) * 16;
    const int bg     = lane >> 3;
    const int b_row  = (lane & 7) + ((bg >> 1) << 3);
    const int b_koff = (bg & 1) * 16;
    const int v_key  = ((lane >> 3) & 1) * 8 + (lane & 7);
    const int v_coff = (lane >> 4) * 16;

    const float scale = 0.125f;
    const float hbias = attn_bias_l[h];

    uint32_t qh[4][4], ql[4][4];
    float oacc[8][4];
    #pragma unroll
    for (int i = 0; i < 8; i++)
        #pragma unroll
        for (int e = 0; e < 4; e++) oacc[i][e] = 0.0f;
    float mr0 = -1e30f, mr1 = -1e30f, lr0 = 0.0f, lr1 = 0.0f;

    for (int t = 0; t < 8; t++) {
        cp_wait<0>();
        __syncthreads();
        if (t + 1 < 8) issue_kv(t + 1);

        if (t == 0) {
            #pragma unroll
            for (int kc = 0; kc < 4; kc++) {
                const uint32_t off = (wq * 16 + a_row) * AT_STRIDE + kc * 32 + a_koff;
                ldm_x4(qh[kc], sb + 0 * AT_TILE + off);
                ldm_x4(ql[kc], sb + 1 * AT_TILE + off);
            }
        }

        const uint32_t stb = sb + AT_STAGE0 + (t & 1) * AT_STAGEB;

        float sacc[8][4];
        #pragma unroll
        for (int i = 0; i < 8; i++)
            #pragma unroll
            for (int e = 0; e < 4; e++) sacc[i][e] = 0.0f;

        #pragma unroll
        for (int kc = 0; kc < 4; kc++) {
            #pragma unroll
            for (int np = 0; np < 4; np++) {
                uint32_t bh[4];
                const uint32_t off = (np * 16 + b_row) * AT_STRIDE + kc * 32 + b_koff;
                ldm_x4(bh, stb + 0 * AT_TILE + off);
                #pragma unroll
                for (int half = 0; half < 2; half++) {
                    const int nt = np * 2 + half, hf = half * 2;
                    uint32_t bf[2] = { bh[hf], bh[hf + 1] };
                    mma_f16(sacc[nt], qh[kc], bf);
                    mma_f16(sacc[nt], ql[kc], bf);
                }
            }
        }

        const int* msp = reinterpret_cast<const int*>(smem + AT_MASK + (t & 1) * 256);
        float vmax0 = -1e30f, vmax1 = -1e30f;
        #pragma unroll
        for (int nt = 0; nt < 8; nt++) {
            const int c0 = nt * 8 + (lane & 3) * 2;
            const int mk0 = msp[c0], mk1 = msp[c0 + 1];
            sacc[nt][0] = mk0 ? sacc[nt][0] * scale + hbias : -1e9f;
            sacc[nt][1] = mk1 ? sacc[nt][1] * scale + hbias : -1e9f;
            sacc[nt][2] = mk0 ? sacc[nt][2] * scale + hbias : -1e9f;
            sacc[nt][3] = mk1 ? sacc[nt][3] * scale + hbias : -1e9f;
            vmax0 = fmaxf(vmax0, fmaxf(sacc[nt][0], sacc[nt][1]));
            vmax1 = fmaxf(vmax1, fmaxf(sacc[nt][2], sacc[nt][3]));
        }
        vmax0 = fmaxf(vmax0, __shfl_xor_sync(0xffffffffu, vmax0, 1));
        vmax0 = fmaxf(vmax0, __shfl_xor_sync(0xffffffffu, vmax0, 2));
        vmax1 = fmaxf(vmax1, __shfl_xor_sync(0xffffffffu, vmax1, 1));
        vmax1 = fmaxf(vmax1, __shfl_xor_sync(0xffffffffu, vmax1, 2));
        const float mn0 = fmaxf(mr0, vmax0);
        const float mn1 = fmaxf(mr1, vmax1);
        const float al0 = __expf(mr0 - mn0);
        const float al1 = __expf(mr1 - mn1);

        uint32_t pah[4][4], pal[4][4];
        float rs0 = 0.0f, rs1 = 0.0f;
        #pragma unroll
        for (int nt = 0; nt < 8; nt++) {
            float p0 = __expf(sacc[nt][0] - mn0);
            float p1 = __expf(sacc[nt][1] - mn0);
            float p2 = __expf(sacc[nt][2] - mn1);
            float p3 = __expf(sacc[nt][3] - mn1);
            rs0 += p0 + p1; rs1 += p2 + p3;
            __half h0, l0, h1, l1, h2, l2, h3, l3;
            split_f16(p0, h0, l0); split_f16(p1, h1, l1);
            split_f16(p2, h2, l2); split_f16(p3, h3, l3);
            const int np = nt >> 1, pos = (nt & 1) * 2;
            __half2 t0; t0.x = h0; t0.y = h1;
            __half2 t1; t1.x = h2; t1.y = h3;
            __half2 t2; t2.x = l0; t2.y = l1;
            __half2 t3; t3.x = l2; t3.y = l3;
            pah[np][pos + 0] = *reinterpret_cast<uint32_t*>(&t0);
            pah[np][pos + 1] = *reinterpret_cast<uint32_t*>(&t1);
            pal[np][pos + 0] = *reinterpret_cast<uint32_t*>(&t2);
            pal[np][pos + 1] = *reinterpret_cast<uint32_t*>(&t3);
        }
        rs0 += __shfl_xor_sync(0xffffffffu, rs0, 1);
        rs0 += __shfl_xor_sync(0xffffffffu, rs0, 2);
        rs1 += __shfl_xor_sync(0xffffffffu, rs1, 1);
        rs1 += __shfl_xor_sync(0xffffffffu, rs1, 2);
        lr0 = lr0 * al0 + rs0;
        lr1 = lr1 * al1 + rs1;
        #pragma unroll
        for (int nt = 0; nt < 8; nt++) {
            oacc[nt][0] *= al0; oacc[nt][1] *= al0;
            oacc[nt][2] *= al1; oacc[nt][3] *= al1;
        }
        mr0 = mn0; mr1 = mn1;

        #pragma unroll
        for (int kc = 0; kc < 4; kc++) {
            #pragma unroll
            for (int np = 0; np < 4; np++) {
                uint32_t vh[4];
                const uint32_t voff = (kc * 16 + v_key) * AT_STRIDE + np * 32 + v_coff;
                ldm_x4_t(vh, stb + 1 * AT_TILE + voff);
                #pragma unroll
                for (int half = 0; half < 2; half++) {
                    const int nt = np * 2 + half, hf = half * 2;
                    uint32_t bf[2] = { vh[hf], vh[hf + 1] };
                    mma_f16(oacc[nt], pah[kc], bf);
                    mma_f16(oacc[nt], pal[kc], bf);
                }
            }
        }
    }

    const float inv0 = 1.0f / lr0;
    const float inv1 = 1.0f / lr1;
    const int row0 = b * Ssz + q0 + wq * 16 + (lane >> 2);
    const int row1 = row0 + 8;
    #pragma unroll
    for (int nt = 0; nt < 8; nt++) {
        const int col = h * HDsz + nt * 8 + (lane & 3) * 2;
        __half2 o0; o0.x = __float2half_rn(oacc[nt][0] * inv0);
        o0.y = __float2half_rn(oacc[nt][1] * inv0);
        __half2 o1; o1.x = __float2half_rn(oacc[nt][2] * inv1);
        o1.y = __float2half_rn(oacc[nt][3] * inv1);
        *reinterpret_cast<__half2*>(O + (size_t)row0 * Dsz + col) = o0;
        *reinterpret_cast<__half2*>(O + (size_t)row1 * Dsz + col) = o1;
    }
}

// ================= fused weight transpose + fp16 convert (single launch) =================
__global__ void wconv_all_kernel(const float* __restrict__ Wq, const float* __restrict__ Wk,
                                 const float* __restrict__ Wv, const float* __restrict__ Wo,
                                 const float* __restrict__ W1, const float* __restrict__ W2,
                                 __half* __restrict__ qkvh, __half* __restrict__ oth,
                                 __half* __restrict__ w1h,  __half* __restrict__ w2h)
{
    const int id = blockIdx.x;
    const int layer = id / 3072;
    const int r = id % 3072;
    const size_t DD = (size_t)Dsz * Dsz;
    const size_t DF = (size_t)Dsz * FFsz;

    const float* src;
    __half* dh;
    int K, N, bx, by;
    if (r < 1024) {
        const int which = r >> 8;
        const int t = r & 255;
        bx = t & 15; by = t >> 4; K = Dsz; N = Dsz;
        if (which == 0)      { src = Wq + layer * DD; dh = qkvh + layer * 3 * DD; }
        else if (which == 1) { src = Wk + layer * DD; dh = qkvh + layer * 3 * DD + DD; }
        else if (which == 2) { src = Wv + layer * DD; dh = qkvh + layer * 3 * DD + 2 * DD; }
        else                 { src = Wo + layer * DD; dh = oth + layer * DD; }
    } else if (r < 2048) {
        const int t = r - 1024;
        bx = t & 63; by = t >> 6; K = Dsz; N = FFsz;
        src = W1 + layer * DF; dh = w1h + layer * DF;
    } else {
        const int t = r - 2048;
        bx = t & 15; by = t >> 4; K = FFsz; N = Dsz;
        src = W2 + layer * DF; dh = w2h + layer * DF;
    }

    __shared__ float tbuf[32][33];
    const int k0 = by * 32, n0 = bx * 32;
    const int x = threadIdx.x, y = threadIdx.y;   // 32 x 8
    #pragma unroll
    for (int i = 0; i < 32; i += 8)
        tbuf[y + i][x] = src[(size_t)(k0 + y + i) * N + n0 + x];
    __syncthreads();
    #pragma unroll
    for (int i = 0; i < 32; i += 8) {
        float v = tbuf[x][y + i];
        dh[(size_t)(n0 + y + i) * K + k0 + x] = __float2half_rn(v);
    }
}

__global__ void bconcat_kernel(const float* __restrict__ bq, const float* __restrict__ bk,
                               const float* __restrict__ bv, float* __restrict__ out)
{
    int l = blockIdx.x, t = threadIdx.x;
    out[l*3*Dsz +          t] = bq[l*Dsz + t];
    out[l*3*Dsz +   Dsz +  t] = bk[l*Dsz + t];
    out[l*3*Dsz + 2*Dsz +  t] = bv[l*Dsz + t];
}

// ================= embedding =================
__global__ void embed_kernel(const int* __restrict__ ids,
                             const float* __restrict__ tok,
                             const float* __restrict__ pos,
                             const float* __restrict__ typ,
                             float* __restrict__ X,
                             __half* __restrict__ Xh)
{
    int row = blockIdx.x;
    int s   = row & (Ssz - 1);
    int c   = threadIdx.x * 4;
    int id  = ids[row];
    float4 t  = *reinterpret_cast<const float4*>(tok + (size_t)id * Dsz + c);
    float4 p  = *reinterpret_cast<const float4*>(pos + (size_t)s  * Dsz + c);
    float4 ty = *reinterpret_cast<const float4*>(typ + c);
    float v[4] = { t.x+p.x+ty.x, t.y+p.y+ty.y, t.z+p.z+ty.z, t.w+p.w+ty.w };
    *reinterpret_cast<float4*>(X + (size_t)row * Dsz + c) = make_float4(v[0],v[1],v[2],v[3]);
    #pragma unroll
    for (int j = 0; j < 4; j++)
        Xh[(size_t)row * Dsz + c + j] = __float2half_rn(v[j]);
}

// ================= add-residual + LayerNorm =================
__device__ __forceinline__ float warp_sum(float v) {
    #pragma unroll
    for (int o = 16; o; o >>= 1) v += __shfl_down_sync(0xffffffffu, v, o);
    return v;
}

__global__ __launch_bounds__(128)
void ln_kernel(const float* __restrict__ X, const float* __restrict__ Dlt,
               const float* __restrict__ gamma, const float* __restrict__ beta,
               float* __restrict__ Out, __half* __restrict__ Oh)
{
    int row = blockIdx.x;
    int tid = threadIdx.x;
    int c   = tid * 4;
    float4 v = *reinterpret_cast<const float4*>(X + (size_t)row * Dsz + c);
    if (Dlt) {
        float4 d = *reinterpret_cast<const float4*>(Dlt + (size_t)row * Dsz + c);
        v.x += d.x; v.y += d.y; v.z += d.z; v.w += d.w;
    }
    float sum = v.x + v.y + v.z + v.w;
    float sq  = v.x*v.x + v.y*v.y + v.z*v.z + v.w*v.w;

    __shared__ float s1[4], s2[4], smn, srd;
    int lane = tid & 31, w = tid >> 5;
    float ws = warp_sum(sum), wq = warp_sum(sq);
    if (lane == 0) { s1[w] = ws; s2[w] = wq; }
    __syncthreads();
    if (tid == 0) {
        float a = s1[0]+s1[1]+s1[2]+s1[3];
        float b = s2[0]+s2[1]+s2[2]+s2[3];
        float mean = a * (1.0f / Dsz);
        float var  = b * (1.0f / Dsz) - mean * mean;
        smn = mean; srd = rsqrtf(var + 1e-5f);
    }
    __syncthreads();
    float mean = smn, rstd = srd;
    float4 g  = *reinterpret_cast<const float4*>(gamma + c);
    float4 be = *reinterpret_cast<const float4*>(beta + c);
    float o[4];
    o[0] = (v.x - mean) * rstd * g.x + be.x;
    o[1] = (v.y - mean) * rstd * g.y + be.y;
    o[2] = (v.z - mean) * rstd * g.z + be.z;
    o[3] = (v.w - mean) * rstd * g.w + be.w;
    *reinterpret_cast<float4*>(Out + (size_t)row * Dsz + c) = make_float4(o[0],o[1],o[2],o[3]);
    if (Oh) {
        #pragma unroll
        for (int j = 0; j < 4; j++)
            Oh[(size_t)row * Dsz + c + j] = __float2half_rn(o[j]);
    }
}

// ================= classifier head =================
__global__ void cls1_kernel(const float* __restrict__ X, const float* __restrict__ W,
                            const float* __restrict__ b, float* __restrict__ out)
{
    int bi = blockIdx.x, j = threadIdx.x;
    const float* x = X + (size_t)(bi * Ssz) * Dsz;
    float s = 0.0f;
    for (int d = 0; d < Dsz; d++) s += x[d] * W[d * 256 + j];
    out[bi * 256 + j] = gelu_exact(s + b[j]);
}
__global__ void cls2_kernel(const float* __restrict__ Hh, const float* __restrict__ W,
                            const float* __restrict__ b, float* __restrict__ out)
{
    int bi = blockIdx.x, j = threadIdx.x;
    const float* x = Hh + bi * 256;
    float s = 0.0f;
    for (int d = 0; d < 256; d++) s += x[d] * W[d * 128 + j];
    out[bi * 128 + j] = gelu_exact(s + b[j]);
}
__global__ void cls3_kernel(const float* __restrict__ Hh, const float* __restrict__ W,
                            const float* __restrict__ b, float* __restrict__ out)
{
    int bi = threadIdx.x;
    const float* x = Hh + bi * 128;
    float s = 0.0f;
    for (int d = 0; d < 128; d++) s += x[d] * W[d];
    out[bi] = s + b[0];
}

// ================= host =================
extern "C" void kernel_launch(void* const* d_in, const int* in_sizes, int n_in,
                              void* d_out, int out_size)
{
    const int*   input_ids      = (const int*)d_in[0];
    const int*   attention_mask = (const int*)d_in[1];
    const float* tok_emb  = (const float*)d_in[2];
    const float* pos_emb  = (const float*)d_in[3];
    const float* type_emb = (const float*)d_in[4];
    const float* Wq  = (const float*)d_in[5];
    const float* bq  = (const float*)d_in[6];
    const float* Wk  = (const float*)d_in[7];
    const float* bk  = (const float*)d_in[8];
    const float* Wv  = (const float*)d_in[9];
    const float* bv  = (const float*)d_in[10];
    const float* Wo  = (const float*)d_in[11];
    const float* bo  = (const float*)d_in[12];
    const float* attn_bias = (const float*)d_in[13];
    const float* ln_a_s = (const float*)d_in[14];
    const float* ln_a_b = (const float*)d_in[15];
    const float* W1  = (const float*)d_in[16];
    const float* b1  = (const float*)d_in[17];
    const float* W2  = (const float*)d_in[18];
    const float* b2  = (const float*)d_in[19];
    const float* ln2_s = (const float*)d_in[20];
    const float* ln2_b = (const float*)d_in[21];
    const float* lnf_s = (const float*)d_in[22];
    const float* lnf_b = (const float*)d_in[23];
    const float* c1W = (const float*)d_in[24];
    const float* c1b = (const float*)d_in[25];
    const float* c2W = (const float*)d_in[26];
    const float* c2b = (const float*)d_in[27];
    const float* c3W = (const float*)d_in[28];
    const float* c3b = (const float*)d_in[29];

    float *pX, *pT, *pbqkv, *pC1, *pC2;
    __half *pXh, *pQKVhi, *pQKVlo, *pOh, *pFh;
    __half *pWqkvh, *pWoth, *pW1th, *pW2th;
    cudaGetSymbolAddress((void**)&pX,    g_X);
    cudaGetSymbolAddress((void**)&pXh,   g_Xh);
    cudaGetSymbolAddress((void**)&pQKVhi, g_QKVhi);
    cudaGetSymbolAddress((void**)&pQKVlo, g_QKVlo);
    cudaGetSymbolAddress((void**)&pOh,   g_Oh);
    cudaGetSymbolAddress((void**)&pT,    g_T);
    cudaGetSymbolAddress((void**)&pFh,   g_Fh);
    cudaGetSymbolAddress((void**)&pWqkvh, g_Wqkv_h);
    cudaGetSymbolAddress((void**)&pWoth, g_Wot_h);
    cudaGetSymbolAddress((void**)&pW1th, g_W1t_h);
    cudaGetSymbolAddress((void**)&pW2th, g_W2t_h);
    cudaGetSymbolAddress((void**)&pbqkv, g_bqkv);
    cudaGetSymbolAddress((void**)&pC1,   g_C1);
    cudaGetSymbolAddress((void**)&pC2,   g_C2);

    cudaFuncSetAttribute(mmagemm_kernel<0>, cudaFuncAttributeMaxDynamicSharedMemorySize, GM_SMEM);
    cudaFuncSetAttribute(mmagemm_kernel<1>, cudaFuncAttributeMaxDynamicSharedMemorySize, GM_SMEM);
    cudaFuncSetAttribute(mmagemm_kernel<2>, cudaFuncAttributeMaxDynamicSharedMemorySize, GM_SMEM);
    cudaFuncSetAttribute(attn_mma_kernel,   cudaFuncAttributeMaxDynamicSharedMemorySize, AT_SMEM);

    // launch #1: all weight conversions in one kernel
    wconv_all_kernel<<<Lsz*3072, dim3(32, 8)>>>(Wq, Wk, Wv, Wo, W1, W2,
        pWqkvh, pWoth, pW1th, pW2th);
    // launch #2
    bconcat_kernel<<<Lsz, Dsz>>>(bq, bk, bv, pbqkv);
    // launch #3
    embed_kernel<<<Msz, 128>>>(input_ids, tok_emb, pos_emb, type_emb, pX, pXh);

    for (int i = 0; i < Lsz; i++) {
        // QKV fused GEMM -> fp16 hi+lo       (launch #4 on first layer)
        mmagemm_kernel<2><<<dim3(3*Dsz/64, Msz/128), 128, GM_SMEM>>>(
            pXh, pWqkvh + (size_t)i*3*Dsz*Dsz,
            pbqkv + i*3*Dsz, nullptr, pQKVhi, pQKVlo, 3*Dsz, Dsz);

        // launch #5 on first layer
        attn_mma_kernel<<<dim3(Ssz/64, Hsz, Bsz), 128, AT_SMEM>>>(
            pQKVhi, pQKVlo, attention_mask, attn_bias + i*Hsz, pOh);

        // Wo GEMM                            (launch #6 on first layer -> ncu target)
        mmagemm_kernel<0><<<dim3(Dsz/64, Msz/128), 128, GM_SMEM>>>(
            pOh, pWoth + (size_t)i*Dsz*Dsz,
            bo + i*Dsz, pT, nullptr, nullptr, Dsz, Dsz);

        ln_kernel<<<Msz, 128>>>(pX, pT, ln_a_s + i*Dsz, ln_a_b + i*Dsz, pX, pXh);

        // FF1 (+GELU -> fp16)
        mmagemm_kernel<1><<<dim3(FFsz/64, Msz/128), 128, GM_SMEM>>>(
            pXh, pW1th + (size_t)i*FFsz*Dsz,
            b1 + i*FFsz, nullptr, pFh, nullptr, FFsz, Dsz);

        // FF2
        mmagemm_kernel<0><<<dim3(Dsz/64, Msz/128), 128, GM_SMEM>>>(
            pFh, pW2th + (size_t)i*Dsz*FFsz,
            b2 + i*Dsz, pT, nullptr, nullptr, Dsz, FFsz);

        ln_kernel<<<Msz, 128>>>(pX, pT, ln2_s + i*Dsz, ln2_b + i*Dsz, pX, pXh);
    }

    ln_kernel<<<Msz, 128>>>(pX, nullptr, lnf_s, lnf_b, pX, nullptr);

    cls1_kernel<<<Bsz, 256>>>(pX, c1W, c1b, pC1);
    cls2_kernel<<<Bsz, 128>>>(pC1, c2W, c2b, pC2);
    cls3_kernel<<<1, Bsz>>>(pC2, c3W, c3b, (float*)d_out);
}

// round 16
// speedup vs baseline: 1.1795x; 1.0600x over previous
#include <cuda_runtime.h>
#include <cuda_fp16.h>
#include <math.h>
#include <stdint.h>

#define Bsz 32
#define Ssz 512
#define Dsz 512
#define Hsz 8
#define Lsz 6
#define FFsz 2048
#define HDsz 64
#define Msz (Bsz*Ssz)          // 16384 rows

// ================= device scratch (no runtime allocation) =================
__device__ float g_X [Msz*Dsz];                 // residual stream fp32
__device__ __half g_Xh [Msz*Dsz];               // activations single fp16
__device__ __half g_QKVhi[Msz*3*Dsz];           // fused QKV out (fp16 hi)
__device__ __half g_QKVlo[Msz*3*Dsz];           // lo plane (only Q region written/used)
__device__ __half g_Oh [Msz*Dsz];               // attention out fp16
__device__ float g_T  [Msz*Dsz];                // GEMM fp32 out (pre-LN)
__device__ __half g_Fh [Msz*FFsz];              // FF hidden fp16
// converted/transposed weights  [N,K] single fp16
__device__ __half g_Wqkv_h[Lsz*3*Dsz*Dsz];
__device__ __half g_Wot_h [Lsz*Dsz*Dsz];
__device__ __half g_W1t_h [Lsz*FFsz*Dsz];
__device__ __half g_W2t_h [Lsz*Dsz*FFsz];
__device__ float g_bqkv[Lsz*3*Dsz];
__device__ float g_C1[Bsz*(Dsz/2)];
__device__ float g_C2[Bsz*(Dsz/4)];

__device__ __forceinline__ float gelu_exact(float x) {
    return 0.5f * x * (1.0f + erff(x * 0.70710678118654752440f));
}
__device__ __forceinline__ void split_f16(float v, __half& h, __half& l) {
    h = __float2half_rn(v);
    l = __float2half_rn(v - __half2float(h));
}

// ================= PTX helpers (sm_80/90 baseline ISA only) =================
__device__ __forceinline__ uint32_t smem_u32(const void* p) {
    uint32_t a;
    asm("{ .reg .u64 t; cvta.to.shared.u64 t, %1; cvt.u32.u64 %0, t; }" : "=r"(a) : "l"(p));
    return a;
}
__device__ __forceinline__ void cp16(uint32_t saddr, const void* g) {
    asm volatile("cp.async.cg.shared.global [%0], [%1], 16;" :: "r"(saddr), "l"(g));
}
__device__ __forceinline__ void cp4(uint32_t saddr, const void* g) {
    asm volatile("cp.async.ca.shared.global [%0], [%1], 4;" :: "r"(saddr), "l"(g));
}
__device__ __forceinline__ void cp_commit() {
    asm volatile("cp.async.commit_group;" ::: "memory");
}
template<int N>
__device__ __forceinline__ void cp_wait() {
    asm volatile("cp.async.wait_group %0;" :: "n"(N) : "memory");
}
__device__ __forceinline__ void ldm_x4(uint32_t* r, uint32_t addr) {
    asm volatile("ldmatrix.sync.aligned.m8n8.x4.shared.b16 {%0,%1,%2,%3}, [%4];"
        : "=r"(r[0]), "=r"(r[1]), "=r"(r[2]), "=r"(r[3]) : "r"(addr));
}
__device__ __forceinline__ void ldm_x4_t(uint32_t* r, uint32_t addr) {
    asm volatile("ldmatrix.sync.aligned.m8n8.x4.trans.shared.b16 {%0,%1,%2,%3}, [%4];"
        : "=r"(r[0]), "=r"(r[1]), "=r"(r[2]), "=r"(r[3]) : "r"(addr));
}
__device__ __forceinline__ void mma_f16(float* d, const uint32_t* a, const uint32_t* b) {
    asm("mma.sync.aligned.m16n8k16.row.col.f32.f16.f16.f32 "
        "{%0,%1,%2,%3}, {%4,%5,%6,%7}, {%8,%9}, {%0,%1,%2,%3};"
        : "+f"(d[0]), "+f"(d[1]), "+f"(d[2]), "+f"(d[3])
        : "r"(a[0]), "r"(a[1]), "r"(a[2]), "r"(a[3]), "r"(b[0]), "r"(b[1]));
}

// ================= fp16 tensor-core GEMM (single-term, BK=64) =================
// C[M,N] = A[M,K] x B[N,K]^T + bias, fp32 accum, single fp16 operands.
// CTA: 128 threads (4 warps, 2m x 2n), tile 128x64, BK=64, 2-stage cp.async,
// single barrier per chunk. 4 CTAs/SM.
// EPI=0: fp32+bias. EPI=1: bias+GELU->fp16. EPI=2: bias->fp16 hi (+lo iff col<Dsz).
#define GM_STRIDE 144                     // bytes per smem row (64 fp16 + 16B pad)
#define GM_TILEA  (128*GM_STRIDE)        // 18432 bytes
#define GM_TILEB  (64*GM_STRIDE)         // 9216 bytes
#define GM_STAGE  (GM_TILEA + GM_TILEB)  // 27648 bytes
#define GM_SMEM   (2*GM_STAGE)           // 55296 bytes

template<int EPI>
__global__ __launch_bounds__(128, 4)
void mmagemm_kernel(const __half* __restrict__ A,
                    const __half* __restrict__ B,
                    const float* __restrict__ bias,
                    float* __restrict__ C,
                    __half* __restrict__ Chi,
                    __half* __restrict__ Clo,
                    int N, int K)
{
    extern __shared__ __align__(16) char smem[];
    const uint32_t sb = smem_u32(smem);

    const int tid  = threadIdx.x;
    const int lane = tid & 31;
    const int wid  = tid >> 5;
    const int wm   = wid >> 1;            // 0..1 (m offset wm*64)
    const int wn   = wid & 1;             // 0..1 (n offset wn*32)

    const int m0 = blockIdx.y * 128;
    const int n0 = blockIdx.x * 64;
    const int nk = K >> 6;                // K / 64 chunks

    auto issue_stage = [&](int stage, int kc) {
        const uint32_t stb = sb + stage * GM_STAGE;
        const int kel = kc * 64;
        #pragma unroll
        for (int p = 0; p < 8; p++) {                 // A: 1024 chunks (128 rows x 8)
            const int c   = p * 128 + tid;
            const int row = c >> 3;
            const int j   = c & 7;
            cp16(stb + row * GM_STRIDE + j * 16,
                 A + (size_t)(m0 + row) * K + kel + j * 8);
        }
        #pragma unroll
        for (int p = 0; p < 4; p++) {                 // B: 512 chunks (64 rows x 8)
            const int c   = p * 128 + tid;
            const int row = c >> 3;
            const int j   = c & 7;
            cp16(stb + GM_TILEA + row * GM_STRIDE + j * 16,
                 B + (size_t)(n0 + row) * K + kel + j * 8);
        }
        cp_commit();
    };

    const int a_row  = (lane & 15);
    const int a_koff = (lane >> 4) * 16;
    const int bg     = lane >> 3;
    const int b_row  = (lane & 7) + ((bg >> 1) << 3);
    const int b_koff = (bg & 1) * 16;

    float acc[4][4][4];
    #pragma unroll
    for (int i = 0; i < 4; i++)
        #pragma unroll
        for (int j = 0; j < 4; j++)
            #pragma unroll
            for (int e = 0; e < 4; e++) acc[i][j][e] = 0.0f;

    issue_stage(0, 0);

    for (int k = 0; k < nk; k++) {
        const int s = k & 1;
        cp_wait<0>();
        __syncthreads();
        if (k + 1 < nk) issue_stage(s ^ 1, k + 1);

        const uint32_t stb = sb + s * GM_STAGE;
        const uint32_t sA = stb;
        const uint32_t sB = stb + GM_TILEA;

        #pragma unroll
        for (int kk = 0; kk < 4; kk++) {              // 4 x k16 within BK=64
            const int kb = kk * 32;
            uint32_t ah[4][4];
            #pragma unroll
            for (int mt = 0; mt < 4; mt++) {
                const uint32_t off = (wm * 64 + mt * 16 + a_row) * GM_STRIDE + kb + a_koff;
                ldm_x4(ah[mt], sA + off);
            }
            uint32_t bh[2][4];
            #pragma unroll
            for (int np = 0; np < 2; np++) {
                const uint32_t off = (wn * 32 + np * 16 + b_row) * GM_STRIDE + kb + b_koff;
                ldm_x4(bh[np], sB + off);
            }
            #pragma unroll
            for (int mt = 0; mt < 4; mt++)
                #pragma unroll
                for (int nt = 0; nt < 4; nt++) {
                    const int np = nt >> 1, hf = (nt & 1) * 2;
                    uint32_t bf[2] = { bh[np][hf], bh[np][hf + 1] };
                    mma_f16(acc[mt][nt], ah[mt], bf);
                }
        }
    }

    const int erow = lane >> 2;
    const int ecol = (lane & 3) * 2;
    #pragma unroll
    for (int mt = 0; mt < 4; mt++) {
        #pragma unroll
        for (int nt = 0; nt < 4; nt++) {
            const int col = n0 + wn * 32 + nt * 8 + ecol;
            const float bx = bias[col], by = bias[col + 1];
            #pragma unroll
            for (int half = 0; half < 2; half++) {
                const int row = m0 + wm * 64 + mt * 16 + erow + half * 8;
                float vx = acc[mt][nt][half * 2 + 0] + bx;
                float vy = acc[mt][nt][half * 2 + 1] + by;
                if (EPI == 0) {
                    float2 v = make_float2(vx, vy);
                    *reinterpret_cast<float2*>(C + (size_t)row * N + col) = v;
                } else if (EPI == 1) {
                    vx = gelu_exact(vx); vy = gelu_exact(vy);
                    __half2 hh; hh.x = __float2half_rn(vx); hh.y = __float2half_rn(vy);
                    *reinterpret_cast<__half2*>(Chi + (size_t)row * N + col) = hh;
                } else {
                    __half h0 = __float2half_rn(vx);
                    __half h1 = __float2half_rn(vy);
                    __half2 hh; hh.x = h0; hh.y = h1;
                    *reinterpret_cast<__half2*>(Chi + (size_t)row * N + col) = hh;
                    if (col < Dsz) {          // lo plane needed only for Q region
                        __half l0 = __float2half_rn(vx - __half2float(h0));
                        __half l1 = __float2half_rn(vy - __half2float(h1));
                        __half2 ll; ll.x = l0; ll.y = l1;
                        *reinterpret_cast<__half2*>(Clo + (size_t)row * N + col) = ll;
                    }
                }
            }
        }
    }
}

// ================= fp16 tensor-core flash attention =================
// Scores: exact-Q 2-term. P@V: single fp16 P (P in [0,1], rel err ~2^-11).
#define AT_STRIDE 144                     // 64 fp16 = 128B + 16B pad
#define AT_TILE   (64*AT_STRIDE)          // 9216
#define AT_STAGE0 (2*AT_TILE)             // Q hi/lo
#define AT_STAGEB (2*AT_TILE)             // K, V (single each)
#define AT_MASK   (AT_STAGE0 + 2*AT_STAGEB)
#define AT_SMEM   (AT_MASK + 512)

__global__ __launch_bounds__(128)
void attn_mma_kernel(const __half* __restrict__ QKVhi,
                     const __half* __restrict__ QKVlo,
                     const int* __restrict__ mask,
                     const float* __restrict__ attn_bias_l,
                     __half* __restrict__ O)
{
    extern __shared__ __align__(16) char smem[];
    const uint32_t sb = smem_u32(smem);

    const int b  = blockIdx.z;
    const int h  = blockIdx.y;
    const int q0 = blockIdx.x * 64;
    const int tid  = threadIdx.x;
    const int lane = tid & 31;
    const int wq   = tid >> 5;
    const int RS   = 3 * Dsz;

    #pragma unroll
    for (int p = 0; p < 8; p++) {                   // Q hi/lo: 1024 chunks
        const int id  = p * 128 + tid;
        const int comp = id >> 9;
        const int cid  = id & 511;
        const int row  = cid >> 3;
        const int j    = cid & 7;
        const __half* src = (comp ? QKVlo : QKVhi)
            + (size_t)(b * Ssz + q0 + row) * RS + h * HDsz + j * 8;
        cp16(sb + comp * AT_TILE + row * AT_STRIDE + j * 16, src);
    }
    cp_commit();

    auto issue_kv = [&](int t) {
        const uint32_t stb = sb + AT_STAGE0 + (t & 1) * AT_STAGEB;
        #pragma unroll
        for (int p = 0; p < 8; p++) {               // K,V single: 1024 chunks
            const int id   = p * 128 + tid;
            const int comp = id >> 9;               // 0=K 1=V
            const int cid  = id & 511;
            const int row  = cid >> 3;
            const int j    = cid & 7;
            const int doff = comp ? 2 * Dsz : Dsz;
            const __half* src = QKVhi
                + (size_t)(b * Ssz + t * 64 + row) * RS + doff + h * HDsz + j * 8;
            cp16(stb + comp * AT_TILE + row * AT_STRIDE + j * 16, src);
        }
        if (tid < 64) cp4(sb + AT_MASK + (t & 1) * 256 + tid * 4, mask + b * Ssz + t * 64 + tid);
        cp_commit();
    };
    issue_kv(0);

    const int a_row  = (lane & 15);
    const int a_koff = (lane >> 4) * 16;
    const int bg     = lane >> 3;
    const int b_row  = (lane & 7) + ((bg >> 1) << 3);
    const int b_koff = (bg & 1) * 16;
    const int v_key  = ((lane >> 3) & 1) * 8 + (lane & 7);
    const int v_coff = (lane >> 4) * 16;

    const float scale = 0.125f;
    const float hbias = attn_bias_l[h];

    uint32_t qh[4][4], ql[4][4];
    float oacc[8][4];
    #pragma unroll
    for (int i = 0; i < 8; i++)
        #pragma unroll
        for (int e = 0; e < 4; e++) oacc[i][e] = 0.0f;
    float mr0 = -1e30f, mr1 = -1e30f, lr0 = 0.0f, lr1 = 0.0f;

    for (int t = 0; t < 8; t++) {
        cp_wait<0>();
        __syncthreads();
        if (t + 1 < 8) issue_kv(t + 1);

        if (t == 0) {
            #pragma unroll
            for (int kc = 0; kc < 4; kc++) {
                const uint32_t off = (wq * 16 + a_row) * AT_STRIDE + kc * 32 + a_koff;
                ldm_x4(qh[kc], sb + 0 * AT_TILE + off);
                ldm_x4(ql[kc], sb + 1 * AT_TILE + off);
            }
        }

        const uint32_t stb = sb + AT_STAGE0 + (t & 1) * AT_STAGEB;

        float sacc[8][4];
        #pragma unroll
        for (int i = 0; i < 8; i++)
            #pragma unroll
            for (int e = 0; e < 4; e++) sacc[i][e] = 0.0f;

        #pragma unroll
        for (int kc = 0; kc < 4; kc++) {
            #pragma unroll
            for (int np = 0; np < 4; np++) {
                uint32_t bh[4];
                const uint32_t off = (np * 16 + b_row) * AT_STRIDE + kc * 32 + b_koff;
                ldm_x4(bh, stb + 0 * AT_TILE + off);
                #pragma unroll
                for (int half = 0; half < 2; half++) {
                    const int nt = np * 2 + half, hf = half * 2;
                    uint32_t bf[2] = { bh[hf], bh[hf + 1] };
                    mma_f16(sacc[nt], qh[kc], bf);
                    mma_f16(sacc[nt], ql[kc], bf);
                }
            }
        }

        const int* msp = reinterpret_cast<const int*>(smem + AT_MASK + (t & 1) * 256);
        float vmax0 = -1e30f, vmax1 = -1e30f;
        #pragma unroll
        for (int nt = 0; nt < 8; nt++) {
            const int c0 = nt * 8 + (lane & 3) * 2;
            const int mk0 = msp[c0], mk1 = msp[c0 + 1];
            sacc[nt][0] = mk0 ? sacc[nt][0] * scale + hbias : -1e9f;
            sacc[nt][1] = mk1 ? sacc[nt][1] * scale + hbias : -1e9f;
            sacc[nt][2] = mk0 ? sacc[nt][2] * scale + hbias : -1e9f;
            sacc[nt][3] = mk1 ? sacc[nt][3] * scale + hbias : -1e9f;
            vmax0 = fmaxf(vmax0, fmaxf(sacc[nt][0], sacc[nt][1]));
            vmax1 = fmaxf(vmax1, fmaxf(sacc[nt][2], sacc[nt][3]));
        }
        vmax0 = fmaxf(vmax0, __shfl_xor_sync(0xffffffffu, vmax0, 1));
        vmax0 = fmaxf(vmax0, __shfl_xor_sync(0xffffffffu, vmax0, 2));
        vmax1 = fmaxf(vmax1, __shfl_xor_sync(0xffffffffu, vmax1, 1));
        vmax1 = fmaxf(vmax1, __shfl_xor_sync(0xffffffffu, vmax1, 2));
        const float mn0 = fmaxf(mr0, vmax0);
        const float mn1 = fmaxf(mr1, vmax1);
        const float al0 = __expf(mr0 - mn0);
        const float al1 = __expf(mr1 - mn1);

        uint32_t pah[4][4];
        float rs0 = 0.0f, rs1 = 0.0f;
        #pragma unroll
        for (int nt = 0; nt < 8; nt++) {
            float p0 = __expf(sacc[nt][0] - mn0);
            float p1 = __expf(sacc[nt][1] - mn0);
            float p2 = __expf(sacc[nt][2] - mn1);
            float p3 = __expf(sacc[nt][3] - mn1);
            rs0 += p0 + p1; rs1 += p2 + p3;
            const int np = nt >> 1, pos = (nt & 1) * 2;
            __half2 t0; t0.x = __float2half_rn(p0); t0.y = __float2half_rn(p1);
            __half2 t1; t1.x = __float2half_rn(p2); t1.y = __float2half_rn(p3);
            pah[np][pos + 0] = *reinterpret_cast<uint32_t*>(&t0);
            pah[np][pos + 1] = *reinterpret_cast<uint32_t*>(&t1);
        }
        rs0 += __shfl_xor_sync(0xffffffffu, rs0, 1);
        rs0 += __shfl_xor_sync(0xffffffffu, rs0, 2);
        rs1 += __shfl_xor_sync(0xffffffffu, rs1, 1);
        rs1 += __shfl_xor_sync(0xffffffffu, rs1, 2);
        lr0 = lr0 * al0 + rs0;
        lr1 = lr1 * al1 + rs1;
        #pragma unroll
        for (int nt = 0; nt < 8; nt++) {
            oacc[nt][0] *= al0; oacc[nt][1] *= al0;
            oacc[nt][2] *= al1; oacc[nt][3] *= al1;
        }
        mr0 = mn0; mr1 = mn1;

        #pragma unroll
        for (int kc = 0; kc < 4; kc++) {
            #pragma unroll
            for (int np = 0; np < 4; np++) {
                uint32_t vh[4];
                const uint32_t voff = (kc * 16 + v_key) * AT_STRIDE + np * 32 + v_coff;
                ldm_x4_t(vh, stb + 1 * AT_TILE + voff);
                #pragma unroll
                for (int half = 0; half < 2; half++) {
                    const int nt = np * 2 + half, hf = half * 2;
                    uint32_t bf[2] = { vh[hf], vh[hf + 1] };
                    mma_f16(oacc[nt], pah[kc], bf);
                }
            }
        }
    }

    const float inv0 = 1.0f / lr0;
    const float inv1 = 1.0f / lr1;
    const int row0 = b * Ssz + q0 + wq * 16 + (lane >> 2);
    const int row1 = row0 + 8;
    #pragma unroll
    for (int nt = 0; nt < 8; nt++) {
        const int col = h * HDsz + nt * 8 + (lane & 3) * 2;
        __half2 o0; o0.x = __float2half_rn(oacc[nt][0] * inv0);
        o0.y = __float2half_rn(oacc[nt][1] * inv0);
        __half2 o1; o1.x = __float2half_rn(oacc[nt][2] * inv1);
        o1.y = __float2half_rn(oacc[nt][3] * inv1);
        *reinterpret_cast<__half2*>(O + (size_t)row0 * Dsz + col) = o0;
        *reinterpret_cast<__half2*>(O + (size_t)row1 * Dsz + col) = o1;
    }
}

// ================= fused weight transpose + fp16 convert (single launch) =================
__global__ void wconv_all_kernel(const float* __restrict__ Wq, const float* __restrict__ Wk,
                                 const float* __restrict__ Wv, const float* __restrict__ Wo,
                                 const float* __restrict__ W1, const float* __restrict__ W2,
                                 __half* __restrict__ qkvh, __half* __restrict__ oth,
                                 __half* __restrict__ w1h,  __half* __restrict__ w2h)
{
    const int id = blockIdx.x;
    const int layer = id / 3072;
    const int r = id % 3072;
    const size_t DD = (size_t)Dsz * Dsz;
    const size_t DF = (size_t)Dsz * FFsz;

    const float* src;
    __half* dh;
    int K, N, bx, by;
    if (r < 1024) {
        const int which = r >> 8;
        const int t = r & 255;
        bx = t & 15; by = t >> 4; K = Dsz; N = Dsz;
        if (which == 0)      { src = Wq + layer * DD; dh = qkvh + layer * 3 * DD; }
        else if (which == 1) { src = Wk + layer * DD; dh = qkvh + layer * 3 * DD + DD; }
        else if (which == 2) { src = Wv + layer * DD; dh = qkvh + layer * 3 * DD + 2 * DD; }
        else                 { src = Wo + layer * DD; dh = oth + layer * DD; }
    } else if (r < 2048) {
        const int t = r - 1024;
        bx = t & 63; by = t >> 6; K = Dsz; N = FFsz;
        src = W1 + layer * DF; dh = w1h + layer * DF;
    } else {
        const int t = r - 2048;
        bx = t & 15; by = t >> 4; K = FFsz; N = Dsz;
        src = W2 + layer * DF; dh = w2h + layer * DF;
    }

    __shared__ float tbuf[32][33];
    const int k0 = by * 32, n0 = bx * 32;
    const int x = threadIdx.x, y = threadIdx.y;   // 32 x 8
    #pragma unroll
    for (int i = 0; i < 32; i += 8)
        tbuf[y + i][x] = src[(size_t)(k0 + y + i) * N + n0 + x];
    __syncthreads();
    #pragma unroll
    for (int i = 0; i < 32; i += 8) {
        float v = tbuf[x][y + i];
        dh[(size_t)(n0 + y + i) * K + k0 + x] = __float2half_rn(v);
    }
}

__global__ void bconcat_kernel(const float* __restrict__ bq, const float* __restrict__ bk,
                               const float* __restrict__ bv, float* __restrict__ out)
{
    int l = blockIdx.x, t = threadIdx.x;
    out[l*3*Dsz +          t] = bq[l*Dsz + t];
    out[l*3*Dsz +   Dsz +  t] = bk[l*Dsz + t];
    out[l*3*Dsz + 2*Dsz +  t] = bv[l*Dsz + t];
}

// ================= embedding =================
__global__ void embed_kernel(const int* __restrict__ ids,
                             const float* __restrict__ tok,
                             const float* __restrict__ pos,
                             const float* __restrict__ typ,
                             float* __restrict__ X,
                             __half* __restrict__ Xh)
{
    int row = blockIdx.x;
    int s   = row & (Ssz - 1);
    int c   = threadIdx.x * 4;
    int id  = ids[row];
    float4 t  = *reinterpret_cast<const float4*>(tok + (size_t)id * Dsz + c);
    float4 p  = *reinterpret_cast<const float4*>(pos + (size_t)s  * Dsz + c);
    float4 ty = *reinterpret_cast<const float4*>(typ + c);
    float v[4] = { t.x+p.x+ty.x, t.y+p.y+ty.y, t.z+p.z+ty.z, t.w+p.w+ty.w };
    *reinterpret_cast<float4*>(X + (size_t)row * Dsz + c) = make_float4(v[0],v[1],v[2],v[3]);
    #pragma unroll
    for (int j = 0; j < 4; j++)
        Xh[(size_t)row * Dsz + c + j] = __float2half_rn(v[j]);
}

// ================= add-residual + LayerNorm =================
__device__ __forceinline__ float warp_sum(float v) {
    #pragma unroll
    for (int o = 16; o; o >>= 1) v += __shfl_down_sync(0xffffffffu, v, o);
    return v;
}

__global__ __launch_bounds__(128)
void ln_kernel(const float* __restrict__ X, const float* __restrict__ Dlt,
               const float* __restrict__ gamma, const float* __restrict__ beta,
               float* __restrict__ Out, __half* __restrict__ Oh)
{
    int row = blockIdx.x;
    int tid = threadIdx.x;
    int c   = tid * 4;
    float4 v = *reinterpret_cast<const float4*>(X + (size_t)row * Dsz + c);
    if (Dlt) {
        float4 d = *reinterpret_cast<const float4*>(Dlt + (size_t)row * Dsz + c);
        v.x += d.x; v.y += d.y; v.z += d.z; v.w += d.w;
    }
    float sum = v.x + v.y + v.z + v.w;
    float sq  = v.x*v.x + v.y*v.y + v.z*v.z + v.w*v.w;

    __shared__ float s1[4], s2[4], smn, srd;
    int lane = tid & 31, w = tid >> 5;
    float ws = warp_sum(sum), wq = warp_sum(sq);
    if (lane == 0) { s1[w] = ws; s2[w] = wq; }
    __syncthreads();
    if (tid == 0) {
        float a = s1[0]+s1[1]+s1[2]+s1[3];
        float b = s2[0]+s2[1]+s2[2]+s2[3];
        float mean = a * (1.0f / Dsz);
        float var  = b * (1.0f / Dsz) - mean * mean;
        smn = mean; srd = rsqrtf(var + 1e-5f);
    }
    __syncthreads();
    float mean = smn, rstd = srd;
    float4 g  = *reinterpret_cast<const float4*>(gamma + c);
    float4 be = *reinterpret_cast<const float4*>(beta + c);
    float o[4];
    o[0] = (v.x - mean) * rstd * g.x + be.x;
    o[1] = (v.y - mean) * rstd * g.y + be.y;
    o[2] = (v.z - mean) * rstd * g.z + be.z;
    o[3] = (v.w - mean) * rstd * g.w + be.w;
    *reinterpret_cast<float4*>(Out + (size_t)row * Dsz + c) = make_float4(o[0],o[1],o[2],o[3]);
    if (Oh) {
        #pragma unroll
        for (int j = 0; j < 4; j++)
            Oh[(size_t)row * Dsz + c + j] = __float2half_rn(o[j]);
    }
}

// ================= classifier head =================
__global__ void cls1_kernel(const float* __restrict__ X, const float* __restrict__ W,
                            const float* __restrict__ b, float* __restrict__ out)
{
    int bi = blockIdx.x, j = threadIdx.x;
    const float* x = X + (size_t)(bi * Ssz) * Dsz;
    float s = 0.0f;
    for (int d = 0; d < Dsz; d++) s += x[d] * W[d * 256 + j];
    out[bi * 256 + j] = gelu_exact(s + b[j]);
}
__global__ void cls2_kernel(const float* __restrict__ Hh, const float* __restrict__ W,
                            const float* __restrict__ b, float* __restrict__ out)
{
    int bi = blockIdx.x, j = threadIdx.x;
    const float* x = Hh + bi * 256;
    float s = 0.0f;
    for (int d = 0; d < 256; d++) s += x[d] * W[d * 128 + j];
    out[bi * 128 + j] = gelu_exact(s + b[j]);
}
__global__ void cls3_kernel(const float* __restrict__ Hh, const float* __restrict__ W,
                            const float* __restrict__ b, float* __restrict__ out)
{
    int bi = threadIdx.x;
    const float* x = Hh + bi * 128;
    float s = 0.0f;
    for (int d = 0; d < 128; d++) s += x[d] * W[d];
    out[bi] = s + b[0];
}

// ================= host =================
extern "C" void kernel_launch(void* const* d_in, const int* in_sizes, int n_in,
                              void* d_out, int out_size)
{
    const int*   input_ids      = (const int*)d_in[0];
    const int*   attention_mask = (const int*)d_in[1];
    const float* tok_emb  = (const float*)d_in[2];
    const float* pos_emb  = (const float*)d_in[3];
    const float* type_emb = (const float*)d_in[4];
    const float* Wq  = (const float*)d_in[5];
    const float* bq  = (const float*)d_in[6];
    const float* Wk  = (const float*)d_in[7];
    const float* bk  = (const float*)d_in[8];
    const float* Wv  = (const float*)d_in[9];
    const float* bv  = (const float*)d_in[10];
    const float* Wo  = (const float*)d_in[11];
    const float* bo  = (const float*)d_in[12];
    const float* attn_bias = (const float*)d_in[13];
    const float* ln_a_s = (const float*)d_in[14];
    const float* ln_a_b = (const float*)d_in[15];
    const float* W1  = (const float*)d_in[16];
    const float* b1  = (const float*)d_in[17];
    const float* W2  = (const float*)d_in[18];
    const float* b2  = (const float*)d_in[19];
    const float* ln2_s = (const float*)d_in[20];
    const float* ln2_b = (const float*)d_in[21];
    const float* lnf_s = (const float*)d_in[22];
    const float* lnf_b = (const float*)d_in[23];
    const float* c1W = (const float*)d_in[24];
    const float* c1b = (const float*)d_in[25];
    const float* c2W = (const float*)d_in[26];
    const float* c2b = (const float*)d_in[27];
    const float* c3W = (const float*)d_in[28];
    const float* c3b = (const float*)d_in[29];

    float *pX, *pT, *pbqkv, *pC1, *pC2;
    __half *pXh, *pQKVhi, *pQKVlo, *pOh, *pFh;
    __half *pWqkvh, *pWoth, *pW1th, *pW2th;
    cudaGetSymbolAddress((void**)&pX,    g_X);
    cudaGetSymbolAddress((void**)&pXh,   g_Xh);
    cudaGetSymbolAddress((void**)&pQKVhi, g_QKVhi);
    cudaGetSymbolAddress((void**)&pQKVlo, g_QKVlo);
    cudaGetSymbolAddress((void**)&pOh,   g_Oh);
    cudaGetSymbolAddress((void**)&pT,    g_T);
    cudaGetSymbolAddress((void**)&pFh,   g_Fh);
    cudaGetSymbolAddress((void**)&pWqkvh, g_Wqkv_h);
    cudaGetSymbolAddress((void**)&pWoth, g_Wot_h);
    cudaGetSymbolAddress((void**)&pW1th, g_W1t_h);
    cudaGetSymbolAddress((void**)&pW2th, g_W2t_h);
    cudaGetSymbolAddress((void**)&pbqkv, g_bqkv);
    cudaGetSymbolAddress((void**)&pC1,   g_C1);
    cudaGetSymbolAddress((void**)&pC2,   g_C2);

    cudaFuncSetAttribute(mmagemm_kernel<0>, cudaFuncAttributeMaxDynamicSharedMemorySize, GM_SMEM);
    cudaFuncSetAttribute(mmagemm_kernel<1>, cudaFuncAttributeMaxDynamicSharedMemorySize, GM_SMEM);
    cudaFuncSetAttribute(mmagemm_kernel<2>, cudaFuncAttributeMaxDynamicSharedMemorySize, GM_SMEM);
    cudaFuncSetAttribute(attn_mma_kernel,   cudaFuncAttributeMaxDynamicSharedMemorySize, AT_SMEM);

    // launch #1: all weight conversions in one kernel
    wconv_all_kernel<<<Lsz*3072, dim3(32, 8)>>>(Wq, Wk, Wv, Wo, W1, W2,
        pWqkvh, pWoth, pW1th, pW2th);
    // launch #2
    bconcat_kernel<<<Lsz, Dsz>>>(bq, bk, bv, pbqkv);
    // launch #3
    embed_kernel<<<Msz, 128>>>(input_ids, tok_emb, pos_emb, type_emb, pX, pXh);

    for (int i = 0; i < Lsz; i++) {
        // QKV fused GEMM -> fp16 hi (+lo for Q cols)   (launch #4 on first layer)
        mmagemm_kernel<2><<<dim3(3*Dsz/64, Msz/128), 128, GM_SMEM>>>(
            pXh, pWqkvh + (size_t)i*3*Dsz*Dsz,
            pbqkv + i*3*Dsz, nullptr, pQKVhi, pQKVlo, 3*Dsz, Dsz);

        // launch #5 on first layer
        attn_mma_kernel<<<dim3(Ssz/64, Hsz, Bsz), 128, AT_SMEM>>>(
            pQKVhi, pQKVlo, attention_mask, attn_bias + i*Hsz, pOh);

        // Wo GEMM                            (launch #6 on first layer -> ncu target)
        mmagemm_kernel<0><<<dim3(Dsz/64, Msz/128), 128, GM_SMEM>>>(
            pOh, pWoth + (size_t)i*Dsz*Dsz,
            bo + i*Dsz, pT, nullptr, nullptr, Dsz, Dsz);

        ln_kernel<<<Msz, 128>>>(pX, pT, ln_a_s + i*Dsz, ln_a_b + i*Dsz, pX, pXh);

        // FF1 (+GELU -> fp16)
        mmagemm_kernel<1><<<dim3(FFsz/64, Msz/128), 128, GM_SMEM>>>(
            pXh, pW1th + (size_t)i*FFsz*Dsz,
            b1 + i*FFsz, nullptr, pFh, nullptr, FFsz, Dsz);

        // FF2
        mmagemm_kernel<0><<<dim3(Dsz/64, Msz/128), 128, GM_SMEM>>>(
            pFh, pW2th + (size_t)i*Dsz*FFsz,
            b2 + i*Dsz, pT, nullptr, nullptr, Dsz, FFsz);

        ln_kernel<<<Msz, 128>>>(pX, pT, ln2_s + i*Dsz, ln2_b + i*Dsz, pX, pXh);
    }

    ln_kernel<<<Msz, 128>>>(pX, nullptr, lnf_s, lnf_b, pX, nullptr);

    cls1_kernel<<<Bsz, 256>>>(pX, c1W, c1b, pC1);
    cls2_kernel<<<Bsz, 128>>>(pC1, c2W, c2b, pC2);
    cls3_kernel<<<1, Bsz>>>(pC2, c3W, c3b, (float*)d_out);
}

// round 17
// speedup vs baseline: 1.1946x; 1.0128x over previous
#include <cuda_runtime.h>
#include <cuda_fp16.h>
#include <math.h>
#include <stdint.h>

#define Bsz 32
#define Ssz 512
#define Dsz 512
#define Hsz 8
#define Lsz 6
#define FFsz 2048
#define HDsz 64
#define Msz (Bsz*Ssz)          // 16384 rows

// ================= device scratch (no runtime allocation) =================
__device__ float g_X [Msz*Dsz];                 // residual stream fp32
__device__ __half g_Xh [Msz*Dsz];               // activations single fp16
__device__ __half g_QKVhi[Msz*3*Dsz];           // fused QKV out (fp16 hi)
__device__ __half g_QKVlo[Msz*3*Dsz];           // lo plane (only Q region written/used)
__device__ __half g_Oh [Msz*Dsz];               // attention out fp16
__device__ __half g_Th [Msz*Dsz];               // GEMM delta out fp16 (pre-LN)
__device__ __half g_Fh [Msz*FFsz];              // FF hidden fp16
// converted/transposed weights  [N,K] single fp16
__device__ __half g_Wqkv_h[Lsz*3*Dsz*Dsz];
__device__ __half g_Wot_h [Lsz*Dsz*Dsz];
__device__ __half g_W1t_h [Lsz*FFsz*Dsz];
__device__ __half g_W2t_h [Lsz*Dsz*FFsz];
__device__ float g_bqkv[Lsz*3*Dsz];
__device__ float g_C1[Bsz*(Dsz/2)];
__device__ float g_C2[Bsz*(Dsz/4)];

__device__ __forceinline__ float gelu_exact(float x) {
    return 0.5f * x * (1.0f + erff(x * 0.70710678118654752440f));
}

// ================= PTX helpers (sm_80/90 baseline ISA only) =================
__device__ __forceinline__ uint32_t smem_u32(const void* p) {
    uint32_t a;
    asm("{ .reg .u64 t; cvta.to.shared.u64 t, %1; cvt.u32.u64 %0, t; }" : "=r"(a) : "l"(p));
    return a;
}
__device__ __forceinline__ void cp16(uint32_t saddr, const void* g) {
    asm volatile("cp.async.cg.shared.global [%0], [%1], 16;" :: "r"(saddr), "l"(g));
}
__device__ __forceinline__ void cp4(uint32_t saddr, const void* g) {
    asm volatile("cp.async.ca.shared.global [%0], [%1], 4;" :: "r"(saddr), "l"(g));
}
__device__ __forceinline__ void cp_commit() {
    asm volatile("cp.async.commit_group;" ::: "memory");
}
template<int N>
__device__ __forceinline__ void cp_wait() {
    asm volatile("cp.async.wait_group %0;" :: "n"(N) : "memory");
}
__device__ __forceinline__ void ldm_x4(uint32_t* r, uint32_t addr) {
    asm volatile("ldmatrix.sync.aligned.m8n8.x4.shared.b16 {%0,%1,%2,%3}, [%4];"
        : "=r"(r[0]), "=r"(r[1]), "=r"(r[2]), "=r"(r[3]) : "r"(addr));
}
__device__ __forceinline__ void ldm_x4_t(uint32_t* r, uint32_t addr) {
    asm volatile("ldmatrix.sync.aligned.m8n8.x4.trans.shared.b16 {%0,%1,%2,%3}, [%4];"
        : "=r"(r[0]), "=r"(r[1]), "=r"(r[2]), "=r"(r[3]) : "r"(addr));
}
__device__ __forceinline__ void mma_f16(float* d, const uint32_t* a, const uint32_t* b) {
    asm("mma.sync.aligned.m16n8k16.row.col.f32.f16.f16.f32 "
        "{%0,%1,%2,%3}, {%4,%5,%6,%7}, {%8,%9}, {%0,%1,%2,%3};"
        : "+f"(d[0]), "+f"(d[1]), "+f"(d[2]), "+f"(d[3])
        : "r"(a[0]), "r"(a[1]), "r"(a[2]), "r"(a[3]), "r"(b[0]), "r"(b[1]));
}

// ================= fp16 tensor-core GEMM (single-term, BK=64) =================
// C[M,N] = A[M,K] x B[N,K]^T + bias, fp32 accum, single fp16 operands.
// CTA: 128 threads (4 warps, 2m x 2n), tile 128x64, BK=64, 2-stage cp.async,
// single barrier per chunk. 4 CTAs/SM.
// EPI=0: bias -> fp16.  EPI=1: bias+GELU -> fp16.  EPI=2: bias -> fp16 hi (+lo iff col<Dsz).
#define GM_STRIDE 144                     // bytes per smem row (64 fp16 + 16B pad)
#define GM_TILEA  (128*GM_STRIDE)        // 18432 bytes
#define GM_TILEB  (64*GM_STRIDE)         // 9216 bytes
#define GM_STAGE  (GM_TILEA + GM_TILEB)  // 27648 bytes
#define GM_SMEM   (2*GM_STAGE)           // 55296 bytes

template<int EPI>
__global__ __launch_bounds__(128, 4)
void mmagemm_kernel(const __half* __restrict__ A,
                    const __half* __restrict__ B,
                    const float* __restrict__ bias,
                    __half* __restrict__ Chi,
                    __half* __restrict__ Clo,
                    int N, int K)
{
    extern __shared__ __align__(16) char smem[];
    const uint32_t sb = smem_u32(smem);

    const int tid  = threadIdx.x;
    const int lane = tid & 31;
    const int wid  = tid >> 5;
    const int wm   = wid >> 1;            // 0..1 (m offset wm*64)
    const int wn   = wid & 1;             // 0..1 (n offset wn*32)

    const int m0 = blockIdx.y * 128;
    const int n0 = blockIdx.x * 64;
    const int nk = K >> 6;                // K / 64 chunks

    auto issue_stage = [&](int stage, int kc) {
        const uint32_t stb = sb + stage * GM_STAGE;
        const int kel = kc * 64;
        #pragma unroll
        for (int p = 0; p < 8; p++) {                 // A: 1024 chunks (128 rows x 8)
            const int c   = p * 128 + tid;
            const int row = c >> 3;
            const int j   = c & 7;
            cp16(stb + row * GM_STRIDE + j * 16,
                 A + (size_t)(m0 + row) * K + kel + j * 8);
        }
        #pragma unroll
        for (int p = 0; p < 4; p++) {                 // B: 512 chunks (64 rows x 8)
            const int c   = p * 128 + tid;
            const int row = c >> 3;
            const int j   = c & 7;
            cp16(stb + GM_TILEA + row * GM_STRIDE + j * 16,
                 B + (size_t)(n0 + row) * K + kel + j * 8);
        }
        cp_commit();
    };

    const int a_row  = (lane & 15);
    const int a_koff = (lane >> 4) * 16;
    const int bg     = lane >> 3;
    const int b_row  = (lane & 7) + ((bg >> 1) << 3);
    const int b_koff = (bg & 1) * 16;

    float acc[4][4][4];
    #pragma unroll
    for (int i = 0; i < 4; i++)
        #pragma unroll
        for (int j = 0; j < 4; j++)
            #pragma unroll
            for (int e = 0; e < 4; e++) acc[i][j][e] = 0.0f;

    issue_stage(0, 0);

    for (int k = 0; k < nk; k++) {
        const int s = k & 1;
        cp_wait<0>();
        __syncthreads();
        if (k + 1 < nk) issue_stage(s ^ 1, k + 1);

        const uint32_t stb = sb + s * GM_STAGE;
        const uint32_t sA = stb;
        const uint32_t sB = stb + GM_TILEA;

        #pragma unroll
        for (int kk = 0; kk < 4; kk++) {              // 4 x k16 within BK=64
            const int kb = kk * 32;
            uint32_t ah[4][4];
            #pragma unroll
            for (int mt = 0; mt < 4; mt++) {
                const uint32_t off = (wm * 64 + mt * 16 + a_row) * GM_STRIDE + kb + a_koff;
                ldm_x4(ah[mt], sA + off);
            }
            uint32_t bh[2][4];
            #pragma unroll
            for (int np = 0; np < 2; np++) {
                const uint32_t off = (wn * 32 + np * 16 + b_row) * GM_STRIDE + kb + b_koff;
                ldm_x4(bh[np], sB + off);
            }
            #pragma unroll
            for (int mt = 0; mt < 4; mt++)
                #pragma unroll
                for (int nt = 0; nt < 4; nt++) {
                    const int np = nt >> 1, hf = (nt & 1) * 2;
                    uint32_t bf[2] = { bh[np][hf], bh[np][hf + 1] };
                    mma_f16(acc[mt][nt], ah[mt], bf);
                }
        }
    }

    const int erow = lane >> 2;
    const int ecol = (lane & 3) * 2;
    #pragma unroll
    for (int mt = 0; mt < 4; mt++) {
        #pragma unroll
        for (int nt = 0; nt < 4; nt++) {
            const int col = n0 + wn * 32 + nt * 8 + ecol;
            const float bx = bias[col], by = bias[col + 1];
            #pragma unroll
            for (int half = 0; half < 2; half++) {
                const int row = m0 + wm * 64 + mt * 16 + erow + half * 8;
                float vx = acc[mt][nt][half * 2 + 0] + bx;
                float vy = acc[mt][nt][half * 2 + 1] + by;
                if (EPI == 1) { vx = gelu_exact(vx); vy = gelu_exact(vy); }
                __half h0 = __float2half_rn(vx);
                __half h1 = __float2half_rn(vy);
                __half2 hh; hh.x = h0; hh.y = h1;
                *reinterpret_cast<__half2*>(Chi + (size_t)row * N + col) = hh;
                if (EPI == 2 && col < Dsz) {      // lo plane needed only for Q region
                    __half l0 = __float2half_rn(vx - __half2float(h0));
                    __half l1 = __float2half_rn(vy - __half2float(h1));
                    __half2 ll; ll.x = l0; ll.y = l1;
                    *reinterpret_cast<__half2*>(Clo + (size_t)row * N + col) = ll;
                }
            }
        }
    }
}

// ================= fp16 tensor-core flash attention =================
// q-tile 128 (8 warps x 16 rows): halves K/V L2 traffic vs 64-row tiles.
// Scores: exact-Q 2-term. P@V: single fp16 P.
#define AT_STRIDE 144                     // 64 fp16 = 128B + 16B pad
#define AT_Q      (128*AT_STRIDE)         // 18432 (Q tile, 128 rows)
#define AT_KV     (64*AT_STRIDE)          // 9216  (K or V tile, 64 rows)
#define AT_STAGE0 (2*AT_Q)                // Q hi/lo
#define AT_STAGEB (2*AT_KV)               // K, V (single each)
#define AT_MASK   (AT_STAGE0 + 2*AT_STAGEB)
#define AT_SMEM   (AT_MASK + 512)

__global__ __launch_bounds__(256)
void attn_mma_kernel(const __half* __restrict__ QKVhi,
                     const __half* __restrict__ QKVlo,
                     const int* __restrict__ mask,
                     const float* __restrict__ attn_bias_l,
                     __half* __restrict__ O)
{
    extern __shared__ __align__(16) char smem[];
    const uint32_t sb = smem_u32(smem);

    const int b  = blockIdx.z;
    const int h  = blockIdx.y;
    const int q0 = blockIdx.x * 128;
    const int tid  = threadIdx.x;
    const int lane = tid & 31;
    const int wq   = tid >> 5;            // 0..7 (16 q rows each)
    const int RS   = 3 * Dsz;

    #pragma unroll
    for (int p = 0; p < 8; p++) {                   // Q hi/lo: 2048 chunks
        const int id  = p * 256 + tid;
        const int comp = id >> 10;                  // 0=hi 1=lo
        const int cid  = id & 1023;
        const int row  = cid >> 3;                  // 0..127
        const int j    = cid & 7;
        const __half* src = (comp ? QKVlo : QKVhi)
            + (size_t)(b * Ssz + q0 + row) * RS + h * HDsz + j * 8;
        cp16(sb + comp * AT_Q + row * AT_STRIDE + j * 16, src);
    }
    cp_commit();

    auto issue_kv = [&](int t) {
        const uint32_t stb = sb + AT_STAGE0 + (t & 1) * AT_STAGEB;
        #pragma unroll
        for (int p = 0; p < 4; p++) {               // K,V single: 1024 chunks
            const int id   = p * 256 + tid;
            const int comp = id >> 9;               // 0=K 1=V
            const int cid  = id & 511;
            const int row  = cid >> 3;
            const int j    = cid & 7;
            const int doff = comp ? 2 * Dsz : Dsz;
            const __half* src = QKVhi
                + (size_t)(b * Ssz + t * 64 + row) * RS + doff + h * HDsz + j * 8;
            cp16(stb + comp * AT_KV + row * AT_STRIDE + j * 16, src);
        }
        if (tid < 64) cp4(sb + AT_MASK + (t & 1) * 256 + tid * 4, mask + b * Ssz + t * 64 + tid);
        cp_commit();
    };
    issue_kv(0);

    const int a_row  = (lane & 15);
    const int a_koff = (lane >> 4) * 16;
    const int bg     = lane >> 3;
    const int b_row  = (lane & 7) + ((bg >> 1) << 3);
    const int b_koff = (bg & 1) * 16;
    const int v_key  = ((lane >> 3) & 1) * 8 + (lane & 7);
    const int v_coff = (lane >> 4) * 16;

    const float scale = 0.125f;
    const float hbias = attn_bias_l[h];

    uint32_t qh[4][4], ql[4][4];
    float oacc[8][4];
    #pragma unroll
    for (int i = 0; i < 8; i++)
        #pragma unroll
        for (int e = 0; e < 4; e++) oacc[i][e] = 0.0f;
    float mr0 = -1e30f, mr1 = -1e30f, lr0 = 0.0f, lr1 = 0.0f;

    for (int t = 0; t < 8; t++) {
        cp_wait<0>();
        __syncthreads();
        if (t + 1 < 8) issue_kv(t + 1);

        if (t == 0) {
            #pragma unroll
            for (int kc = 0; kc < 4; kc++) {
                const uint32_t off = (wq * 16 + a_row) * AT_STRIDE + kc * 32 + a_koff;
                ldm_x4(qh[kc], sb + 0 * AT_Q + off);
                ldm_x4(ql[kc], sb + 1 * AT_Q + off);
            }
        }

        const uint32_t stb = sb + AT_STAGE0 + (t & 1) * AT_STAGEB;

        float sacc[8][4];
        #pragma unroll
        for (int i = 0; i < 8; i++)
            #pragma unroll
            for (int e = 0; e < 4; e++) sacc[i][e] = 0.0f;

        #pragma unroll
        for (int kc = 0; kc < 4; kc++) {
            #pragma unroll
            for (int np = 0; np < 4; np++) {
                uint32_t bh[4];
                const uint32_t off = (np * 16 + b_row) * AT_STRIDE + kc * 32 + b_koff;
                ldm_x4(bh, stb + 0 * AT_KV + off);
                #pragma unroll
                for (int half = 0; half < 2; half++) {
                    const int nt = np * 2 + half, hf = half * 2;
                    uint32_t bf[2] = { bh[hf], bh[hf + 1] };
                    mma_f16(sacc[nt], qh[kc], bf);
                    mma_f16(sacc[nt], ql[kc], bf);
                }
            }
        }

        const int* msp = reinterpret_cast<const int*>(smem + AT_MASK + (t & 1) * 256);
        float vmax0 = -1e30f, vmax1 = -1e30f;
        #pragma unroll
        for (int nt = 0; nt < 8; nt++) {
            const int c0 = nt * 8 + (lane & 3) * 2;
            const int mk0 = msp[c0], mk1 = msp[c0 + 1];
            sacc[nt][0] = mk0 ? sacc[nt][0] * scale + hbias : -1e9f;
            sacc[nt][1] = mk1 ? sacc[nt][1] * scale + hbias : -1e9f;
            sacc[nt][2] = mk0 ? sacc[nt][2] * scale + hbias : -1e9f;
            sacc[nt][3] = mk1 ? sacc[nt][3] * scale + hbias : -1e9f;
            vmax0 = fmaxf(vmax0, fmaxf(sacc[nt][0], sacc[nt][1]));
            vmax1 = fmaxf(vmax1, fmaxf(sacc[nt][2], sacc[nt][3]));
        }
        vmax0 = fmaxf(vmax0, __shfl_xor_sync(0xffffffffu, vmax0, 1));
        vmax0 = fmaxf(vmax0, __shfl_xor_sync(0xffffffffu, vmax0, 2));
        vmax1 = fmaxf(vmax1, __shfl_xor_sync(0xffffffffu, vmax1, 1));
        vmax1 = fmaxf(vmax1, __shfl_xor_sync(0xffffffffu, vmax1, 2));
        const float mn0 = fmaxf(mr0, vmax0);
        const float mn1 = fmaxf(mr1, vmax1);
        const float al0 = __expf(mr0 - mn0);
        const float al1 = __expf(mr1 - mn1);

        uint32_t pah[4][4];
        float rs0 = 0.0f, rs1 = 0.0f;
        #pragma unroll
        for (int nt = 0; nt < 8; nt++) {
            float p0 = __expf(sacc[nt][0] - mn0);
            float p1 = __expf(sacc[nt][1] - mn0);
            float p2 = __expf(sacc[nt][2] - mn1);
            float p3 = __expf(sacc[nt][3] - mn1);
            rs0 += p0 + p1; rs1 += p2 + p3;
            const int np = nt >> 1, pos = (nt & 1) * 2;
            __half2 t0; t0.x = __float2half_rn(p0); t0.y = __float2half_rn(p1);
            __half2 t1; t1.x = __float2half_rn(p2); t1.y = __float2half_rn(p3);
            pah[np][pos + 0] = *reinterpret_cast<uint32_t*>(&t0);
            pah[np][pos + 1] = *reinterpret_cast<uint32_t*>(&t1);
        }
        rs0 += __shfl_xor_sync(0xffffffffu, rs0, 1);
        rs0 += __shfl_xor_sync(0xffffffffu, rs0, 2);
        rs1 += __shfl_xor_sync(0xffffffffu, rs1, 1);
        rs1 += __shfl_xor_sync(0xffffffffu, rs1, 2);
        lr0 = lr0 * al0 + rs0;
        lr1 = lr1 * al1 + rs1;
        #pragma unroll
        for (int nt = 0; nt < 8; nt++) {
            oacc[nt][0] *= al0; oacc[nt][1] *= al0;
            oacc[nt][2] *= al1; oacc[nt][3] *= al1;
        }
        mr0 = mn0; mr1 = mn1;

        #pragma unroll
        for (int kc = 0; kc < 4; kc++) {
            #pragma unroll
            for (int np = 0; np < 4; np++) {
                uint32_t vh[4];
                const uint32_t voff = (kc * 16 + v_key) * AT_STRIDE + np * 32 + v_coff;
                ldm_x4_t(vh, stb + 1 * AT_KV + voff);
                #pragma unroll
                for (int half = 0; half < 2; half++) {
                    const int nt = np * 2 + half, hf = half * 2;
                    uint32_t bf[2] = { vh[hf], vh[hf + 1] };
                    mma_f16(oacc[nt], pah[kc], bf);
                }
            }
        }
    }

    const float inv0 = 1.0f / lr0;
    const float inv1 = 1.0f / lr1;
    const int row0 = b * Ssz + q0 + wq * 16 + (lane >> 2);
    const int row1 = row0 + 8;
    #pragma unroll
    for (int nt = 0; nt < 8; nt++) {
        const int col = h * HDsz + nt * 8 + (lane & 3) * 2;
        __half2 o0; o0.x = __float2half_rn(oacc[nt][0] * inv0);
        o0.y = __float2half_rn(oacc[nt][1] * inv0);
        __half2 o1; o1.x = __float2half_rn(oacc[nt][2] * inv1);
        o1.y = __float2half_rn(oacc[nt][3] * inv1);
        *reinterpret_cast<__half2*>(O + (size_t)row0 * Dsz + col) = o0;
        *reinterpret_cast<__half2*>(O + (size_t)row1 * Dsz + col) = o1;
    }
}

// ================= fused weight transpose + fp16 convert (single launch) =================
__global__ void wconv_all_kernel(const float* __restrict__ Wq, const float* __restrict__ Wk,
                                 const float* __restrict__ Wv, const float* __restrict__ Wo,
                                 const float* __restrict__ W1, const float* __restrict__ W2,
                                 __half* __restrict__ qkvh, __half* __restrict__ oth,
                                 __half* __restrict__ w1h,  __half* __restrict__ w2h)
{
    const int id = blockIdx.x;
    const int layer = id / 3072;
    const int r = id % 3072;
    const size_t DD = (size_t)Dsz * Dsz;
    const size_t DF = (size_t)Dsz * FFsz;

    const float* src;
    __half* dh;
    int K, N, bx, by;
    if (r < 1024) {
        const int which = r >> 8;
        const int t = r & 255;
        bx = t & 15; by = t >> 4; K = Dsz; N = Dsz;
        if (which == 0)      { src = Wq + layer * DD; dh = qkvh + layer * 3 * DD; }
        else if (which == 1) { src = Wk + layer * DD; dh = qkvh + layer * 3 * DD + DD; }
        else if (which == 2) { src = Wv + layer * DD; dh = qkvh + layer * 3 * DD + 2 * DD; }
        else                 { src = Wo + layer * DD; dh = oth + layer * DD; }
    } else if (r < 2048) {
        const int t = r - 1024;
        bx = t & 63; by = t >> 6; K = Dsz; N = FFsz;
        src = W1 + layer * DF; dh = w1h + layer * DF;
    } else {
        const int t = r - 2048;
        bx = t & 15; by = t >> 4; K = FFsz; N = Dsz;
        src = W2 + layer * DF; dh = w2h + layer * DF;
    }

    __shared__ float tbuf[32][33];
    const int k0 = by * 32, n0 = bx * 32;
    const int x = threadIdx.x, y = threadIdx.y;   // 32 x 8
    #pragma unroll
    for (int i = 0; i < 32; i += 8)
        tbuf[y + i][x] = src[(size_t)(k0 + y + i) * N + n0 + x];
    __syncthreads();
    #pragma unroll
    for (int i = 0; i < 32; i += 8) {
        float v = tbuf[x][y + i];
        dh[(size_t)(n0 + y + i) * K + k0 + x] = __float2half_rn(v);
    }
}

__global__ void bconcat_kernel(const float* __restrict__ bq, const float* __restrict__ bk,
                               const float* __restrict__ bv, float* __restrict__ out)
{
    int l = blockIdx.x, t = threadIdx.x;
    out[l*3*Dsz +          t] = bq[l*Dsz + t];
    out[l*3*Dsz +   Dsz +  t] = bk[l*Dsz + t];
    out[l*3*Dsz + 2*Dsz +  t] = bv[l*Dsz + t];
}

// ================= embedding =================
__global__ void embed_kernel(const int* __restrict__ ids,
                             const float* __restrict__ tok,
                             const float* __restrict__ pos,
                             const float* __restrict__ typ,
                             float* __restrict__ X,
                             __half* __restrict__ Xh)
{
    int row = blockIdx.x;
    int s   = row & (Ssz - 1);
    int c   = threadIdx.x * 4;
    int id  = ids[row];
    float4 t  = *reinterpret_cast<const float4*>(tok + (size_t)id * Dsz + c);
    float4 p  = *reinterpret_cast<const float4*>(pos + (size_t)s  * Dsz + c);
    float4 ty = *reinterpret_cast<const float4*>(typ + c);
    float v[4] = { t.x+p.x+ty.x, t.y+p.y+ty.y, t.z+p.z+ty.z, t.w+p.w+ty.w };
    *reinterpret_cast<float4*>(X + (size_t)row * Dsz + c) = make_float4(v[0],v[1],v[2],v[3]);
    #pragma unroll
    for (int j = 0; j < 4; j++)
        Xh[(size_t)row * Dsz + c + j] = __float2half_rn(v[j]);
}

// ================= add-residual + LayerNorm (delta in fp16) =================
__device__ __forceinline__ float warp_sum(float v) {
    #pragma unroll
    for (int o = 16; o; o >>= 1) v += __shfl_down_sync(0xffffffffu, v, o);
    return v;
}

__global__ __launch_bounds__(128)
void ln_kernel(const float* __restrict__ X, const __half* __restrict__ Dlt,
               const float* __restrict__ gamma, const float* __restrict__ beta,
               float* __restrict__ Out, __half* __restrict__ Oh)
{
    int row = blockIdx.x;
    int tid = threadIdx.x;
    int c   = tid * 4;
    float4 v = *reinterpret_cast<const float4*>(X + (size_t)row * Dsz + c);
    if (Dlt) {
        __half2 d01 = *reinterpret_cast<const __half2*>(Dlt + (size_t)row * Dsz + c);
        __half2 d23 = *reinterpret_cast<const __half2*>(Dlt + (size_t)row * Dsz + c + 2);
        v.x += __half2float(d01.x); v.y += __half2float(d01.y);
        v.z += __half2float(d23.x); v.w += __half2float(d23.y);
    }
    float sum = v.x + v.y + v.z + v.w;
    float sq  = v.x*v.x + v.y*v.y + v.z*v.z + v.w*v.w;

    __shared__ float s1[4], s2[4], smn, srd;
    int lane = tid & 31, w = tid >> 5;
    float ws = warp_sum(sum), wq = warp_sum(sq);
    if (lane == 0) { s1[w] = ws; s2[w] = wq; }
    __syncthreads();
    if (tid == 0) {
        float a = s1[0]+s1[1]+s1[2]+s1[3];
        float b = s2[0]+s2[1]+s2[2]+s2[3];
        float mean = a * (1.0f / Dsz);
        float var  = b * (1.0f / Dsz) - mean * mean;
        smn = mean; srd = rsqrtf(var + 1e-5f);
    }
    __syncthreads();
    float mean = smn, rstd = srd;
    float4 g  = *reinterpret_cast<const float4*>(gamma + c);
    float4 be = *reinterpret_cast<const float4*>(beta + c);
    float o[4];
    o[0] = (v.x - mean) * rstd * g.x + be.x;
    o[1] = (v.y - mean) * rstd * g.y + be.y;
    o[2] = (v.z - mean) * rstd * g.z + be.z;
    o[3] = (v.w - mean) * rstd * g.w + be.w;
    *reinterpret_cast<float4*>(Out + (size_t)row * Dsz + c) = make_float4(o[0],o[1],o[2],o[3]);
    if (Oh) {
        #pragma unroll
        for (int j = 0; j < 4; j++)
            Oh[(size_t)row * Dsz + c + j] = __float2half_rn(o[j]);
    }
}

// ================= classifier head =================
__global__ void cls1_kernel(const float* __restrict__ X, const float* __restrict__ W,
                            const float* __restrict__ b, float* __restrict__ out)
{
    int bi = blockIdx.x, j = threadIdx.x;
    const float* x = X + (size_t)(bi * Ssz) * Dsz;
    float s = 0.0f;
    for (int d = 0; d < Dsz; d++) s += x[d] * W[d * 256 + j];
    out[bi * 256 + j] = gelu_exact(s + b[j]);
}
__global__ void cls2_kernel(const float* __restrict__ Hh, const float* __restrict__ W,
                            const float* __restrict__ b, float* __restrict__ out)
{
    int bi = blockIdx.x, j = threadIdx.x;
    const float* x = Hh + bi * 256;
    float s = 0.0f;
    for (int d = 0; d < 256; d++) s += x[d] * W[d * 128 + j];
    out[bi * 128 + j] = gelu_exact(s + b[j]);
}
__global__ void cls3_kernel(const float* __restrict__ Hh, const float* __restrict__ W,
                            const float* __restrict__ b, float* __restrict__ out)
{
    int bi = threadIdx.x;
    const float* x = Hh + bi * 128;
    float s = 0.0f;
    for (int d = 0; d < 128; d++) s += x[d] * W[d];
    out[bi] = s + b[0];
}

// ================= host =================
extern "C" void kernel_launch(void* const* d_in, const int* in_sizes, int n_in,
                              void* d_out, int out_size)
{
    const int*   input_ids      = (const int*)d_in[0];
    const int*   attention_mask = (const int*)d_in[1];
    const float* tok_emb  = (const float*)d_in[2];
    const float* pos_emb  = (const float*)d_in[3];
    const float* type_emb = (const float*)d_in[4];
    const float* Wq  = (const float*)d_in[5];
    const float* bq  = (const float*)d_in[6];
    const float* Wk  = (const float*)d_in[7];
    const float* bk  = (const float*)d_in[8];
    const float* Wv  = (const float*)d_in[9];
    const float* bv  = (const float*)d_in[10];
    const float* Wo  = (const float*)d_in[11];
    const float* bo  = (const float*)d_in[12];
    const float* attn_bias = (const float*)d_in[13];
    const float* ln_a_s = (const float*)d_in[14];
    const float* ln_a_b = (const float*)d_in[15];
    const float* W1  = (const float*)d_in[16];
    const float* b1  = (const float*)d_in[17];
    const float* W2  = (const float*)d_in[18];
    const float* b2  = (const float*)d_in[19];
    const float* ln2_s = (const float*)d_in[20];
    const float* ln2_b = (const float*)d_in[21];
    const float* lnf_s = (const float*)d_in[22];
    const float* lnf_b = (const float*)d_in[23];
    const float* c1W = (const float*)d_in[24];
    const float* c1b = (const float*)d_in[25];
    const float* c2W = (const float*)d_in[26];
    const float* c2b = (const float*)d_in[27];
    const float* c3W = (const float*)d_in[28];
    const float* c3b = (const float*)d_in[29];

    float *pX, *pbqkv, *pC1, *pC2;
    __half *pXh, *pQKVhi, *pQKVlo, *pOh, *pTh, *pFh;
    __half *pWqkvh, *pWoth, *pW1th, *pW2th;
    cudaGetSymbolAddress((void**)&pX,    g_X);
    cudaGetSymbolAddress((void**)&pXh,   g_Xh);
    cudaGetSymbolAddress((void**)&pQKVhi, g_QKVhi);
    cudaGetSymbolAddress((void**)&pQKVlo, g_QKVlo);
    cudaGetSymbolAddress((void**)&pOh,   g_Oh);
    cudaGetSymbolAddress((void**)&pTh,   g_Th);
    cudaGetSymbolAddress((void**)&pFh,   g_Fh);
    cudaGetSymbolAddress((void**)&pWqkvh, g_Wqkv_h);
    cudaGetSymbolAddress((void**)&pWoth, g_Wot_h);
    cudaGetSymbolAddress((void**)&pW1th, g_W1t_h);
    cudaGetSymbolAddress((void**)&pW2th, g_W2t_h);
    cudaGetSymbolAddress((void**)&pbqkv, g_bqkv);
    cudaGetSymbolAddress((void**)&pC1,   g_C1);
    cudaGetSymbolAddress((void**)&pC2,   g_C2);

    cudaFuncSetAttribute(mmagemm_kernel<0>, cudaFuncAttributeMaxDynamicSharedMemorySize, GM_SMEM);
    cudaFuncSetAttribute(mmagemm_kernel<1>, cudaFuncAttributeMaxDynamicSharedMemorySize, GM_SMEM);
    cudaFuncSetAttribute(mmagemm_kernel<2>, cudaFuncAttributeMaxDynamicSharedMemorySize, GM_SMEM);
    cudaFuncSetAttribute(attn_mma_kernel,   cudaFuncAttributeMaxDynamicSharedMemorySize, AT_SMEM);

    // launch #1: all weight conversions in one kernel
    wconv_all_kernel<<<Lsz*3072, dim3(32, 8)>>>(Wq, Wk, Wv, Wo, W1, W2,
        pWqkvh, pWoth, pW1th, pW2th);
    // launch #2
    bconcat_kernel<<<Lsz, Dsz>>>(bq, bk, bv, pbqkv);
    // launch #3
    embed_kernel<<<Msz, 128>>>(input_ids, tok_emb, pos_emb, type_emb, pX, pXh);

    for (int i = 0; i < Lsz; i++) {
        // QKV fused GEMM -> fp16 hi (+lo for Q cols)   (launch #4 on first layer)
        mmagemm_kernel<2><<<dim3(3*Dsz/64, Msz/128), 128, GM_SMEM>>>(
            pXh, pWqkvh + (size_t)i*3*Dsz*Dsz,
            pbqkv + i*3*Dsz, pQKVhi, pQKVlo, 3*Dsz, Dsz);

        // launch #5 on first layer
        attn_mma_kernel<<<dim3(Ssz/128, Hsz, Bsz), 256, AT_SMEM>>>(
            pQKVhi, pQKVlo, attention_mask, attn_bias + i*Hsz, pOh);

        // Wo GEMM -> fp16 delta              (launch #6 on first layer -> ncu target)
        mmagemm_kernel<0><<<dim3(Dsz/64, Msz/128), 128, GM_SMEM>>>(
            pOh, pWoth + (size_t)i*Dsz*Dsz,
            bo + i*Dsz, pTh, nullptr, Dsz, Dsz);

        ln_kernel<<<Msz, 128>>>(pX, pTh, ln_a_s + i*Dsz, ln_a_b + i*Dsz, pX, pXh);

        // FF1 (+GELU -> fp16)
        mmagemm_kernel<1><<<dim3(FFsz/64, Msz/128), 128, GM_SMEM>>>(
            pXh, pW1th + (size_t)i*FFsz*Dsz,
            b1 + i*FFsz, pFh, nullptr, FFsz, Dsz);

        // FF2 -> fp16 delta
        mmagemm_kernel<0><<<dim3(Dsz/64, Msz/128), 128, GM_SMEM>>>(
            pFh, pW2th + (size_t)i*Dsz*FFsz,
            b2 + i*Dsz, pTh, nullptr, Dsz, FFsz);

        ln_kernel<<<Msz, 128>>>(pX, pTh, ln2_s + i*Dsz, ln2_b + i*Dsz, pX, pXh);
    }

    ln_kernel<<<Msz, 128>>>(pX, nullptr, lnf_s, lnf_b, pX, nullptr);

    cls1_kernel<<<Bsz, 256>>>(pX, c1W, c1b, pC1);
    cls2_kernel<<<Bsz, 128>>>(pC1, c2W, c2b, pC2);
    cls3_kernel<<<1, Bsz>>>(pC2, c3W, c3b, (float*)d_out);
}